// round 11
// baseline (speedup 1.0000x reference)
#include <cuda_runtime.h>
#include <cuda_bf16.h>
#include <cstdint>
#include <math.h>

#define BATCH 64
#define NNODE 512
#define NEDGE 4
#define CIN   64
#define CHID  128
#define COUT  16

// ---- mma.sync GEMM tiling ----
#define KC 32                               // K per pipeline chunk
#define NSTG 3                              // pipeline stages
#define ASTR 80                             // A smem row stride bytes (32 bf16 + 16 pad)
#define HSTR 272                            // H smem row stride bytes (128 bf16 + 8 pad)
#define OFF_AHI 0
#define OFF_ALO (128 * ASTR)                // 10240
#define OFF_HHI (2 * 128 * ASTR)            // 20480
#define OFF_HLO (2 * 128 * ASTR + KC * HSTR)
#define STAGEB  (2 * 128 * ASTR + 2 * KC * HSTR)   // 37888
#define SMEM_DYN (NSTG * STAGEB)                    // 113664 -> 2 CTAs/SM

// ---------------- device scratch (zero-initialized at module load) ----------------
__device__ float          g_deg  [BATCH * NNODE * NEDGE];
__device__ int            g_idx  [BATCH * NNODE];                   // compact slot -> node
__device__ int            g_cnt  [BATCH];                           // masked-node count
__device__ __nv_bfloat16  g_Achi [(size_t)BATCH * NNODE * NNODE];   // rows compact, cols full
__device__ __nv_bfloat16  g_Aclo [(size_t)BATCH * NNODE * NNODE];
__device__ __nv_bfloat16  g_Acchi[(size_t)BATCH * NNODE * NNODE];   // rows+cols compact
__device__ __nv_bfloat16  g_Acclo[(size_t)BATCH * NNODE * NNODE];
__device__ __nv_bfloat16  g_Hhi  [(size_t)BATCH * NNODE * CHID];    // [b][k][n]
__device__ __nv_bfloat16  g_Hlo  [(size_t)BATCH * NNODE * CHID];
__device__ float          g_hout [(size_t)BATCH * NNODE * CHID];    // layer-1 out (compact rows)
__device__ float          g_part [BATCH * 4 * CHID];                // pooled partials

// ---------------- PTX helpers ----------------
__device__ __forceinline__ uint32_t smem_u32(const void* p) {
    uint32_t a;
    asm("{ .reg .u64 t; cvta.to.shared.u64 t, %1; cvt.u32.u64 %0, t; }" : "=r"(a) : "l"(p));
    return a;
}
__device__ __forceinline__ void cp16(uint32_t dst, const void* src) {
    asm volatile("cp.async.cg.shared.global [%0], [%1], 16;" :: "r"(dst), "l"(src));
}
#define CP_COMMIT() asm volatile("cp.async.commit_group;" ::: "memory")
#define CP_WAIT1()  asm volatile("cp.async.wait_group 1;"  ::: "memory")

__device__ __forceinline__ void ldm_x4(uint32_t& r0, uint32_t& r1, uint32_t& r2, uint32_t& r3,
                                       uint32_t a) {
    asm volatile("ldmatrix.sync.aligned.m8n8.x4.shared.b16 {%0,%1,%2,%3}, [%4];"
                 : "=r"(r0), "=r"(r1), "=r"(r2), "=r"(r3) : "r"(a));
}
__device__ __forceinline__ void ldm_x4t(uint32_t& r0, uint32_t& r1, uint32_t& r2, uint32_t& r3,
                                        uint32_t a) {
    asm volatile("ldmatrix.sync.aligned.m8n8.x4.trans.shared.b16 {%0,%1,%2,%3}, [%4];"
                 : "=r"(r0), "=r"(r1), "=r"(r2), "=r"(r3) : "r"(a));
}
__device__ __forceinline__ void mma16816(float* c, const uint32_t* a, uint32_t b0, uint32_t b1) {
    asm volatile(
        "mma.sync.aligned.m16n8k16.row.col.f32.bf16.bf16.f32 "
        "{%0,%1,%2,%3}, {%4,%5,%6,%7}, {%8,%9}, {%0,%1,%2,%3};"
        : "+f"(c[0]), "+f"(c[1]), "+f"(c[2]), "+f"(c[3])
        : "r"(a[0]), "r"(a[1]), "r"(a[2]), "r"(a[3]), "r"(b0), "r"(b1));
}

// ---------------- K1: degrees -> rsqrt(max(sum,1)) ----------------
__global__ void deg_kernel(const float* __restrict__ adj) {
    int bi = blockIdx.x;
    int i  = bi & (NNODE - 1);
    const float4* row = (const float4*)(adj + (size_t)bi * (NNODE * NEDGE));
    int j = threadIdx.x;
    float4 v0 = row[j];
    float4 v1 = row[j + 128];
    float4 v2 = row[j + 256];
    float4 v3 = row[j + 384];
    if (j == i)         v0 = make_float4(1.f, 1.f, 1.f, 1.f);
    if (j + 128 == i)   v1 = make_float4(1.f, 1.f, 1.f, 1.f);
    if (j + 256 == i)   v2 = make_float4(1.f, 1.f, 1.f, 1.f);
    if (j + 384 == i)   v3 = make_float4(1.f, 1.f, 1.f, 1.f);
    float4 s;
    s.x = (v0.x + v1.x) + (v2.x + v3.x);
    s.y = (v0.y + v1.y) + (v2.y + v3.y);
    s.z = (v0.z + v1.z) + (v2.z + v3.z);
    s.w = (v0.w + v1.w) + (v2.w + v3.w);
    for (int o = 16; o > 0; o >>= 1) {
        s.x += __shfl_down_sync(0xffffffffu, s.x, o);
        s.y += __shfl_down_sync(0xffffffffu, s.y, o);
        s.z += __shfl_down_sync(0xffffffffu, s.z, o);
        s.w += __shfl_down_sync(0xffffffffu, s.w, o);
    }
    __shared__ float4 sh[4];
    int lane = threadIdx.x & 31, w = threadIdx.x >> 5;
    if (lane == 0) sh[w] = s;
    __syncthreads();
    if (threadIdx.x == 0) {
        float4 t = sh[0];
        t.x += sh[1].x + sh[2].x + sh[3].x;
        t.y += sh[1].y + sh[2].y + sh[3].y;
        t.z += sh[1].z + sh[2].z + sh[3].z;
        t.w += sh[1].w + sh[2].w + sh[3].w;
        float4 r;
        r.x = rsqrtf(fmaxf(t.x, 1.f));
        r.y = rsqrtf(fmaxf(t.y, 1.f));
        r.z = rsqrtf(fmaxf(t.z, 1.f));
        r.w = rsqrtf(fmaxf(t.w, 1.f));
        ((float4*)g_deg)[bi] = r;
    }
}

// ---------------- K2: deterministic mask compaction ----------------
__global__ void compact_kernel(const int* __restrict__ mask) {
    __shared__ int woff[17];
    int b = blockIdx.x, t = threadIdx.x, lane = t & 31, w = t >> 5;
    int m = mask[b * NNODE + t];
    unsigned bal = __ballot_sync(0xffffffffu, m != 0);
    if (lane == 0) woff[w + 1] = __popc(bal);
    if (t == 0) woff[0] = 0;
    __syncthreads();
    if (t == 0) for (int k = 1; k <= 16; k++) woff[k] += woff[k - 1];
    __syncthreads();
    if (m) {
        int rank = woff[w] + __popc(bal & ((1u << lane) - 1u));
        g_idx[b * NNODE + rank] = t;
    }
    if (t == 0) g_cnt[b] = woff[16];
}

// ---------------- K3: build compacted normalized adjacency (Ac + Acc) ----------------
// one CTA (128 thr) per (b, compact row ri); reads only masked adj rows
__global__ __launch_bounds__(128)
void buildA_kernel(const float* __restrict__ adj) {
    int blk = blockIdx.x;
    int b = blk >> 9, ri = blk & (NNODE - 1);
    int cnt = g_cnt[b];
    if (ri >= cnt) return;
    int i = g_idx[b * NNODE + ri];
    int t = threadIdx.x;

    const float4* row = (const float4*)(adj + ((size_t)(b * NNODE + i)) * (NNODE * NEDGE));
    float4 di = ((const float4*)g_deg)[b * NNODE + i];

    __shared__ __nv_bfloat16 shi[NNODE], slo[NNODE];
    __shared__ __nv_bfloat16 schi[NNODE], sclo[NNODE];

#pragma unroll
    for (int q = 0; q < 4; q++) {
        int j = t + q * 128;
        float4 a = row[j];
        if (j == i) a = make_float4(1.f, 1.f, 1.f, 1.f);
        float4 dj = ((const float4*)g_deg)[b * NNODE + j];
        float v = a.x * di.x * dj.x + a.y * di.y * dj.y + a.z * di.z * dj.z + a.w * di.w * dj.w;
        __nv_bfloat16 hi = __float2bfloat16(v);
        shi[j] = hi;
        slo[j] = __float2bfloat16(v - __bfloat162float(hi));
    }
    __syncthreads();

    size_t rowOff = ((size_t)(b * NNODE + ri)) * NNODE;
    // Ac: full 512 cols, vector copy from smem (1KB per array)
    ((uint2*)(g_Achi + rowOff))[t] = ((const uint2*)shi)[t];
    ((uint2*)(g_Aclo + rowOff))[t] = ((const uint2*)slo)[t];

    // Acc: gather masked cols into compact order
    for (int rj = t; rj < cnt; rj += 128) {
        int j = g_idx[b * NNODE + rj];
        schi[rj] = shi[j];
        sclo[rj] = slo[j];
    }
    // zero tail up to 8B boundary
    int cntPad = (cnt + 3) & ~3;
    for (int rj = cnt + t; rj < cntPad; rj += 128) { schi[rj] = __float2bfloat16(0.f); sclo[rj] = __float2bfloat16(0.f); }
    __syncthreads();
    int nW = cntPad >> 2;   // uint2 count (4 bf16 each)
    for (int w2 = t; w2 < nW; w2 += 128) {
        ((uint2*)(g_Acchi + rowOff))[w2] = ((const uint2*)schi)[w2];
        ((uint2*)(g_Acclo + rowOff))[w2] = ((const uint2*)sclo)[w2];
    }
}

// ---------------- K4: lin: H[b][k][n] (hi/lo bf16) = X @ W ----------------
__global__ __launch_bounds__(256)
void lin_kernel(const float* __restrict__ X, const float* __restrict__ W, int K,
                __nv_bfloat16* __restrict__ Hhi, __nv_bfloat16* __restrict__ Hlo,
                const int* __restrict__ cnt) {
    int b  = blockIdx.x >> 2;
    int rt = blockIdx.x & 3;
    if (cnt && rt * 128 >= cnt[b]) return;   // compact mode: skip empty tiles
    const float* Xb = X + (size_t)(b * NNODE + rt * 128) * K;

    __shared__ float As[8][128];
    __shared__ float Bs[8][128];

    int tid = threadIdx.x;
    int tx = tid & 15, ty = tid >> 4;

    float acc[8][8];
#pragma unroll
    for (int u = 0; u < 8; u++)
#pragma unroll
        for (int v = 0; v < 8; v++) acc[u][v] = 0.f;

    int arow = tid >> 1, acol = (tid & 1) * 4;
    int brow = tid >> 5, bcol = (tid & 31) * 4;

    for (int k0 = 0; k0 < K; k0 += 8) {
        float4 a = *(const float4*)(Xb + (size_t)arow * K + k0 + acol);
        As[acol + 0][arow] = a.x;
        As[acol + 1][arow] = a.y;
        As[acol + 2][arow] = a.z;
        As[acol + 3][arow] = a.w;
        *(float4*)(&Bs[brow][bcol]) = *(const float4*)(W + (size_t)(k0 + brow) * CHID + bcol);
        __syncthreads();
#pragma unroll
        for (int kk = 0; kk < 8; kk++) {
            float ra[8], rb[8];
            *(float4*)(ra)     = *(const float4*)(&As[kk][ty * 8]);
            *(float4*)(ra + 4) = *(const float4*)(&As[kk][ty * 8 + 4]);
            *(float4*)(rb)     = *(const float4*)(&Bs[kk][tx * 8]);
            *(float4*)(rb + 4) = *(const float4*)(&Bs[kk][tx * 8 + 4]);
#pragma unroll
            for (int u = 0; u < 8; u++)
#pragma unroll
                for (int v = 0; v < 8; v++)
                    acc[u][v] = fmaf(ra[u], rb[v], acc[u][v]);
        }
        __syncthreads();
    }

#pragma unroll
    for (int u = 0; u < 8; u++) {
        int row = ty * 8 + u;
        size_t base = ((size_t)(b * NNODE + rt * 128 + row)) * CHID + tx * 8;
        __nv_bfloat16 hi8[8], lo8[8];
#pragma unroll
        for (int v = 0; v < 8; v++) {
            float val = acc[u][v];
            __nv_bfloat16 hi = __float2bfloat16(val);
            hi8[v] = hi;
            lo8[v] = __float2bfloat16(val - __bfloat162float(hi));
        }
        *(uint4*)(Hhi + base) = *(const uint4*)hi8;
        *(uint4*)(Hlo + base) = *(const uint4*)lo8;
    }
}

// ---------------- K5: mma.sync GCN GEMM on compacted rows ----------------
__device__ __forceinline__ void load_chunk(uint32_t st, int c, int tid,
                                           const char* Ah, const char* Al,
                                           const char* Bh, const char* Bl) {
#pragma unroll
    for (int i = 0; i < 2; i++) {
        int item = tid + i * 256;
        int row = item >> 2, seg = item & 3;
        uint32_t so = (uint32_t)(row * ASTR + seg * 16);
        size_t   go = (size_t)row * (NNODE * 2) + (size_t)c * (KC * 2) + seg * 16;
        cp16(st + OFF_AHI + so, Ah + go);
        cp16(st + OFF_ALO + so, Al + go);
    }
#pragma unroll
    for (int i = 0; i < 2; i++) {
        int item = tid + i * 256;
        int kr = item >> 4, seg = item & 15;
        uint32_t so = (uint32_t)(kr * HSTR + seg * 16);
        size_t   go = (size_t)(c * KC + kr) * (CHID * 2) + seg * 16;
        cp16(st + OFF_HHI + so, Bh + go);
        cp16(st + OFF_HLO + so, Bl + go);
    }
    CP_COMMIT();
}

template<bool POOL>
__global__ __launch_bounds__(256, 2)
void gcn_mma_kernel(const __nv_bfloat16* __restrict__ Ahi, const __nv_bfloat16* __restrict__ Alo,
                    const __nv_bfloat16* __restrict__ Hhi, const __nv_bfloat16* __restrict__ Hlo,
                    const float* __restrict__ bias, const int* __restrict__ cntArr,
                    int kfull, float* __restrict__ Hout, float* __restrict__ part) {
    int b = blockIdx.x >> 2, tile = blockIdx.x & 3;
    int cnt = cntArr[b];
    if (tile * 128 >= cnt) return;                       // nothing to compute (part stays 0)
    int nch = kfull ? (NNODE / KC) : ((((cnt + 127) >> 7) << 7) / KC);   // K chunks

    extern __shared__ char smem[];
    uint32_t sb = smem_u32(smem);
    int tid = threadIdx.x;
    int wid = tid >> 5, lane = tid & 31;
    int warpM = wid >> 2, warpN = wid & 3;

    const char* Ah = (const char*)Ahi + ((size_t)(b * NNODE + tile * 128)) * (NNODE * 2);
    const char* Al = (const char*)Alo + ((size_t)(b * NNODE + tile * 128)) * (NNODE * 2);
    const char* Bh = (const char*)Hhi + ((size_t)b * NNODE) * (CHID * 2);
    const char* Bl = (const char*)Hlo + ((size_t)b * NNODE) * (CHID * 2);

    uint32_t aRow = (uint32_t)((warpM * 64 + (lane & 15)) * ASTR + (lane >> 4) * 16);
    uint32_t bRow = (uint32_t)(((lane & 7) + ((lane >> 3) & 1) * 8) * HSTR
                               + (warpN * 32 + ((lane >> 4) & 1) * 8) * 2);

    load_chunk(sb, 0, tid, Ah, Al, Bh, Bl);
    load_chunk(sb + STAGEB, 1, tid, Ah, Al, Bh, Bl);

    float acc[4][4][4];
#pragma unroll
    for (int m = 0; m < 4; m++)
#pragma unroll
        for (int n = 0; n < 4; n++)
#pragma unroll
            for (int k = 0; k < 4; k++) acc[m][n][k] = 0.f;

    int stg = 0;
    for (int c = 0; c < nch; c++) {
        CP_WAIT1();
        __syncthreads();
        int pstg = stg + 2; if (pstg >= NSTG) pstg -= NSTG;
        if (c + 2 < nch)
            load_chunk(sb + (uint32_t)pstg * STAGEB, c + 2, tid, Ah, Al, Bh, Bl);
        else
            CP_COMMIT();
        uint32_t st = sb + (uint32_t)stg * STAGEB;
#pragma unroll
        for (int ks = 0; ks < KC / 16; ks++) {
            uint32_t ahi[4][4], alo[4][4];
#pragma unroll
            for (int mt = 0; mt < 4; mt++) {
                uint32_t ad = st + aRow + (uint32_t)(mt * 16 * ASTR + ks * 32);
                ldm_x4(ahi[mt][0], ahi[mt][1], ahi[mt][2], ahi[mt][3], ad + OFF_AHI);
                ldm_x4(alo[mt][0], alo[mt][1], alo[mt][2], alo[mt][3], ad + OFF_ALO);
            }
            uint32_t bhi[2][4], blo[2][4];
#pragma unroll
            for (int ng = 0; ng < 2; ng++) {
                uint32_t bd = st + bRow + (uint32_t)(ks * 16 * HSTR + ng * 32);
                ldm_x4t(bhi[ng][0], bhi[ng][1], bhi[ng][2], bhi[ng][3], bd + OFF_HHI);
                ldm_x4t(blo[ng][0], blo[ng][1], blo[ng][2], blo[ng][3], bd + OFF_HLO);
            }
#pragma unroll
            for (int mt = 0; mt < 4; mt++)
#pragma unroll
                for (int nt = 0; nt < 4; nt++) {
                    int ng = nt >> 1, hf = nt & 1;
                    mma16816(acc[mt][nt], ahi[mt], bhi[ng][hf * 2], bhi[ng][hf * 2 + 1]);
                    mma16816(acc[mt][nt], ahi[mt], blo[ng][hf * 2], blo[ng][hf * 2 + 1]);
                    mma16816(acc[mt][nt], alo[mt], bhi[ng][hf * 2], bhi[ng][hf * 2 + 1]);
                }
        }
        if (++stg >= NSTG) stg = 0;
    }

    // epilogue: bias + silu; rows >= cnt forced to exact 0 (pad rows)
    int lim = cnt - tile * 128;                     // valid rows in this tile
    int rowBase = b * NNODE + tile * 128 + warpM * 64;
    float* Ob = Hout + (size_t)rowBase * CHID;
    float csum[8];
#pragma unroll
    for (int k = 0; k < 8; k++) csum[k] = 0.f;

#pragma unroll
    for (int mt = 0; mt < 4; mt++) {
        int lr0 = warpM * 64 + mt * 16 + (lane >> 2);   // local row in tile
        bool ok0 = lr0 < lim;
        bool ok1 = (lr0 + 8) < lim;
#pragma unroll
        for (int nt = 0; nt < 4; nt++) {
            int col = warpN * 32 + nt * 8 + (lane & 3) * 2;
            float b0v = bias[col], b1v = bias[col + 1];
            float z0 = ok0 ? (acc[mt][nt][0] + b0v) : 0.f;
            float z1 = ok0 ? (acc[mt][nt][1] + b1v) : 0.f;
            float z2 = ok1 ? (acc[mt][nt][2] + b0v) : 0.f;
            float z3 = ok1 ? (acc[mt][nt][3] + b1v) : 0.f;
            float o0 = z0 / (1.f + __expf(-z0));
            float o1 = z1 / (1.f + __expf(-z1));
            float o2 = z2 / (1.f + __expf(-z2));
            float o3 = z3 / (1.f + __expf(-z3));
            if (POOL) {
                csum[nt * 2]     += o0 + o2;
                csum[nt * 2 + 1] += o1 + o3;
            } else {
                int r0 = mt * 16 + (lane >> 2);
                *(float2*)(Ob + (size_t)r0 * CHID + col)       = make_float2(o0, o1);
                *(float2*)(Ob + (size_t)(r0 + 8) * CHID + col) = make_float2(o2, o3);
            }
        }
    }

    if (POOL) {
        __shared__ float spool[2][CHID];
#pragma unroll
        for (int off = 4; off < 32; off <<= 1)
#pragma unroll
            for (int k = 0; k < 8; k++)
                csum[k] += __shfl_xor_sync(0xffffffffu, csum[k], off);
        if ((lane >> 2) == 0) {
#pragma unroll
            for (int nt = 0; nt < 4; nt++) {
                int col = warpN * 32 + nt * 8 + (lane & 3) * 2;
                spool[warpM][col]     = csum[nt * 2];
                spool[warpM][col + 1] = csum[nt * 2 + 1];
            }
        }
        __syncthreads();
        if (tid < CHID)
            part[(b * 4 + tile) * CHID + tid] = spool[0][tid] + spool[1][tid];
    }
}

// ---------------- K6: head from pooled partials ----------------
__global__ void head_kernel(const float* __restrict__ part,
                            const float* __restrict__ Wl1, const float* __restrict__ bl1,
                            const float* __restrict__ Wl2, const float* __restrict__ bl2,
                            float* __restrict__ out) {
    int b = blockIdx.x;
    int c = threadIdx.x;     // 128 threads
    __shared__ float g[CHID], g1[CHID];
    const float* pb = part + b * 4 * CHID;
    g[c] = (pb[c] + pb[CHID + c] + pb[2 * CHID + c] + pb[3 * CHID + c]) * (1.0f / NNODE);
    __syncthreads();
    float acc = bl1[c];
    for (int k = 0; k < CHID; k++) acc = fmaf(g[k], Wl1[k * CHID + c], acc);
    g1[c] = acc / (1.f + __expf(-acc));
    __syncthreads();
    if (c < COUT) {
        float acc2 = bl2[c];
        for (int k = 0; k < CHID; k++) acc2 = fmaf(g1[k], Wl2[k * COUT + c], acc2);
        out[b * COUT + c] = acc2;
    }
}

// ---------------- launch ----------------
extern "C" void kernel_launch(void* const* d_in, const int* in_sizes, int n_in,
                              void* d_out, int out_size) {
    const float* x    = (const float*)d_in[0];
    const float* adj  = (const float*)d_in[1];
    const int*   mask = (const int*)  d_in[2];
    const float* W0   = (const float*)d_in[3];
    const float* b0   = (const float*)d_in[4];
    const float* W1   = (const float*)d_in[5];
    const float* b1   = (const float*)d_in[6];
    const float* Wl1  = (const float*)d_in[7];
    const float* bl1  = (const float*)d_in[8];
    const float* Wl2  = (const float*)d_in[9];
    const float* bl2  = (const float*)d_in[10];
    float* out = (float*)d_out;

    __nv_bfloat16 *dAchi, *dAclo, *dAcchi, *dAcclo, *dHhi, *dHlo;
    float *dHout, *dPart;
    int *dCnt;
    cudaGetSymbolAddress((void**)&dAchi,  g_Achi);
    cudaGetSymbolAddress((void**)&dAclo,  g_Aclo);
    cudaGetSymbolAddress((void**)&dAcchi, g_Acchi);
    cudaGetSymbolAddress((void**)&dAcclo, g_Acclo);
    cudaGetSymbolAddress((void**)&dHhi,   g_Hhi);
    cudaGetSymbolAddress((void**)&dHlo,   g_Hlo);
    cudaGetSymbolAddress((void**)&dHout,  g_hout);
    cudaGetSymbolAddress((void**)&dPart,  g_part);
    cudaGetSymbolAddress((void**)&dCnt,   g_cnt);

    static int smem_set = 0;
    if (!smem_set) {
        cudaFuncSetAttribute(gcn_mma_kernel<false>,
                             cudaFuncAttributeMaxDynamicSharedMemorySize, SMEM_DYN);
        cudaFuncSetAttribute(gcn_mma_kernel<true>,
                             cudaFuncAttributeMaxDynamicSharedMemorySize, SMEM_DYN);
        smem_set = 1;
    }

    // 1) degrees (full pass: normalization needs all nodes)
    deg_kernel<<<BATCH * NNODE, 128>>>(adj);
    // 2) mask compaction (idx, cnt)
    compact_kernel<<<BATCH, NNODE>>>(mask);
    // 3) compacted normalized adjacency: Ac (rows compact) + Acc (rows+cols compact)
    buildA_kernel<<<BATCH * NNODE, 128>>>(adj);
    // 4) H = x @ W0 (dense, all nodes feed layer-1 K)
    lin_kernel<<<BATCH * 4, 256>>>(x, W0, CIN, dHhi, dHlo, nullptr);
    // 5) layer 1: compact rows, full K=512
    gcn_mma_kernel<false><<<BATCH * 4, 256, SMEM_DYN>>>(dAchi, dAclo, dHhi, dHlo, b0,
                                                        dCnt, 1, dHout, dPart);
    // 6) Hc = h1c @ W1 (compact rows)
    lin_kernel<<<BATCH * 4, 256>>>(dHout, W1, CHID, dHhi, dHlo, dCnt);
    // 7) layer 2: compact rows AND compact K, fused mean-pool
    gcn_mma_kernel<true><<<BATCH * 4, 256, SMEM_DYN>>>(dAcchi, dAcclo, dHhi, dHlo, b1,
                                                       dCnt, 0, dHout, dPart);
    // 8) MLP head
    head_kernel<<<BATCH, CHID>>>(dPart, Wl1, bl1, Wl2, bl2, out);
}

// round 12
// speedup vs baseline: 1.0011x; 1.0011x over previous
#include <cuda_runtime.h>
#include <cuda_bf16.h>
#include <cstdint>
#include <math.h>

#define BATCH 64
#define NNODE 512
#define NEDGE 4
#define CIN   64
#define CHID  128
#define COUT  16

// ---- mma.sync GEMM tiling ----
#define KC 32                               // K per pipeline chunk
#define NSTG 3                              // pipeline stages
#define ASTR 80                             // A smem row stride bytes (32 bf16 + 16 pad)
#define HSTR 272                            // H smem row stride bytes (128 bf16 + 8 pad)
#define OFF_AHI 0
#define OFF_ALO (128 * ASTR)                // 10240
#define OFF_HHI (2 * 128 * ASTR)            // 20480
#define OFF_HLO (2 * 128 * ASTR + KC * HSTR)
#define STAGEB  (2 * 128 * ASTR + 2 * KC * HSTR)   // 37888
#define SMEM_DYN (NSTG * STAGEB)                    // 113664 -> 2 CTAs/SM

// ---------------- device scratch (zero-initialized at module load) ----------------
__device__ float          g_deg  [BATCH * NNODE * NEDGE];
__device__ int            g_idx  [BATCH * NNODE];                   // compact slot -> node
__device__ int            g_cnt  [BATCH];                           // masked-node count
__device__ __nv_bfloat16  g_Achi [(size_t)BATCH * NNODE * NNODE];   // rows compact, cols full
__device__ __nv_bfloat16  g_Aclo [(size_t)BATCH * NNODE * NNODE];
__device__ __nv_bfloat16  g_Acchi[(size_t)BATCH * NNODE * NNODE];   // rows+cols compact
__device__ __nv_bfloat16  g_Acclo[(size_t)BATCH * NNODE * NNODE];
__device__ __nv_bfloat16  g_Hhi  [(size_t)BATCH * NNODE * CHID];    // [b][k][n]
__device__ __nv_bfloat16  g_Hlo  [(size_t)BATCH * NNODE * CHID];
__device__ float          g_hout [(size_t)BATCH * NNODE * CHID];    // layer-1 out (compact rows)
__device__ float          g_part [BATCH * 4 * CHID];                // pooled partials

// ---------------- PTX helpers ----------------
__device__ __forceinline__ uint32_t smem_u32(const void* p) {
    uint32_t a;
    asm("{ .reg .u64 t; cvta.to.shared.u64 t, %1; cvt.u32.u64 %0, t; }" : "=r"(a) : "l"(p));
    return a;
}
__device__ __forceinline__ void cp16(uint32_t dst, const void* src) {
    asm volatile("cp.async.cg.shared.global [%0], [%1], 16;" :: "r"(dst), "l"(src));
}
#define CP_COMMIT() asm volatile("cp.async.commit_group;" ::: "memory")
#define CP_WAIT1()  asm volatile("cp.async.wait_group 1;"  ::: "memory")

__device__ __forceinline__ void ldm_x4(uint32_t& r0, uint32_t& r1, uint32_t& r2, uint32_t& r3,
                                       uint32_t a) {
    asm volatile("ldmatrix.sync.aligned.m8n8.x4.shared.b16 {%0,%1,%2,%3}, [%4];"
                 : "=r"(r0), "=r"(r1), "=r"(r2), "=r"(r3) : "r"(a));
}
__device__ __forceinline__ void ldm_x4t(uint32_t& r0, uint32_t& r1, uint32_t& r2, uint32_t& r3,
                                        uint32_t a) {
    asm volatile("ldmatrix.sync.aligned.m8n8.x4.trans.shared.b16 {%0,%1,%2,%3}, [%4];"
                 : "=r"(r0), "=r"(r1), "=r"(r2), "=r"(r3) : "r"(a));
}
__device__ __forceinline__ void mma16816(float* c, const uint32_t* a, uint32_t b0, uint32_t b1) {
    asm volatile(
        "mma.sync.aligned.m16n8k16.row.col.f32.bf16.bf16.f32 "
        "{%0,%1,%2,%3}, {%4,%5,%6,%7}, {%8,%9}, {%0,%1,%2,%3};"
        : "+f"(c[0]), "+f"(c[1]), "+f"(c[2]), "+f"(c[3])
        : "r"(a[0]), "r"(a[1]), "r"(a[2]), "r"(a[3]), "r"(b0), "r"(b1));
}

// ---------------- K1: degrees -> rsqrt(max(sum,1)) ----------------
__global__ void deg_kernel(const float* __restrict__ adj) {
    int bi = blockIdx.x;
    int i  = bi & (NNODE - 1);
    const float4* row = (const float4*)(adj + (size_t)bi * (NNODE * NEDGE));
    int j = threadIdx.x;
    float4 v0 = row[j];
    float4 v1 = row[j + 128];
    float4 v2 = row[j + 256];
    float4 v3 = row[j + 384];
    if (j == i)         v0 = make_float4(1.f, 1.f, 1.f, 1.f);
    if (j + 128 == i)   v1 = make_float4(1.f, 1.f, 1.f, 1.f);
    if (j + 256 == i)   v2 = make_float4(1.f, 1.f, 1.f, 1.f);
    if (j + 384 == i)   v3 = make_float4(1.f, 1.f, 1.f, 1.f);
    float4 s;
    s.x = (v0.x + v1.x) + (v2.x + v3.x);
    s.y = (v0.y + v1.y) + (v2.y + v3.y);
    s.z = (v0.z + v1.z) + (v2.z + v3.z);
    s.w = (v0.w + v1.w) + (v2.w + v3.w);
    for (int o = 16; o > 0; o >>= 1) {
        s.x += __shfl_down_sync(0xffffffffu, s.x, o);
        s.y += __shfl_down_sync(0xffffffffu, s.y, o);
        s.z += __shfl_down_sync(0xffffffffu, s.z, o);
        s.w += __shfl_down_sync(0xffffffffu, s.w, o);
    }
    __shared__ float4 sh[4];
    int lane = threadIdx.x & 31, w = threadIdx.x >> 5;
    if (lane == 0) sh[w] = s;
    __syncthreads();
    if (threadIdx.x == 0) {
        float4 t = sh[0];
        t.x += sh[1].x + sh[2].x + sh[3].x;
        t.y += sh[1].y + sh[2].y + sh[3].y;
        t.z += sh[1].z + sh[2].z + sh[3].z;
        t.w += sh[1].w + sh[2].w + sh[3].w;
        float4 r;
        r.x = rsqrtf(fmaxf(t.x, 1.f));
        r.y = rsqrtf(fmaxf(t.y, 1.f));
        r.z = rsqrtf(fmaxf(t.z, 1.f));
        r.w = rsqrtf(fmaxf(t.w, 1.f));
        ((float4*)g_deg)[bi] = r;
    }
}

// ---------------- K2: deterministic mask compaction ----------------
__global__ void compact_kernel(const int* __restrict__ mask) {
    __shared__ int woff[17];
    int b = blockIdx.x, t = threadIdx.x, lane = t & 31, w = t >> 5;
    int m = mask[b * NNODE + t];
    unsigned bal = __ballot_sync(0xffffffffu, m != 0);
    if (lane == 0) woff[w + 1] = __popc(bal);
    if (t == 0) woff[0] = 0;
    __syncthreads();
    if (t == 0) for (int k = 1; k <= 16; k++) woff[k] += woff[k - 1];
    __syncthreads();
    if (m) {
        int rank = woff[w] + __popc(bal & ((1u << lane) - 1u));
        g_idx[b * NNODE + rank] = t;
    }
    if (t == 0) g_cnt[b] = woff[16];
}

// ---------------- K3: build compacted normalized adjacency (Ac + Acc) ----------------
// one CTA (128 thr) per (b, compact row ri); reads only masked adj rows
__global__ __launch_bounds__(128)
void buildA_kernel(const float* __restrict__ adj) {
    int blk = blockIdx.x;
    int b = blk >> 9, ri = blk & (NNODE - 1);
    int cnt = g_cnt[b];
    if (ri >= cnt) return;
    int i = g_idx[b * NNODE + ri];
    int t = threadIdx.x;

    const float4* row = (const float4*)(adj + ((size_t)(b * NNODE + i)) * (NNODE * NEDGE));
    float4 di = ((const float4*)g_deg)[b * NNODE + i];

    __shared__ __nv_bfloat16 shi[NNODE], slo[NNODE];
    __shared__ __nv_bfloat16 schi[NNODE], sclo[NNODE];

#pragma unroll
    for (int q = 0; q < 4; q++) {
        int j = t + q * 128;
        float4 a = row[j];
        if (j == i) a = make_float4(1.f, 1.f, 1.f, 1.f);
        float4 dj = ((const float4*)g_deg)[b * NNODE + j];
        float v = a.x * di.x * dj.x + a.y * di.y * dj.y + a.z * di.z * dj.z + a.w * di.w * dj.w;
        __nv_bfloat16 hi = __float2bfloat16(v);
        shi[j] = hi;
        slo[j] = __float2bfloat16(v - __bfloat162float(hi));
    }
    __syncthreads();

    size_t rowOff = ((size_t)(b * NNODE + ri)) * NNODE;
    // Ac: full 512 cols, vector copy from smem (1KB per array)
    ((uint2*)(g_Achi + rowOff))[t] = ((const uint2*)shi)[t];
    ((uint2*)(g_Aclo + rowOff))[t] = ((const uint2*)slo)[t];

    // Acc: gather masked cols into compact order
    for (int rj = t; rj < cnt; rj += 128) {
        int j = g_idx[b * NNODE + rj];
        schi[rj] = shi[j];
        sclo[rj] = slo[j];
    }
    // zero tail up to 8B boundary
    int cntPad = (cnt + 3) & ~3;
    for (int rj = cnt + t; rj < cntPad; rj += 128) { schi[rj] = __float2bfloat16(0.f); sclo[rj] = __float2bfloat16(0.f); }
    __syncthreads();
    int nW = cntPad >> 2;   // uint2 count (4 bf16 each)
    for (int w2 = t; w2 < nW; w2 += 128) {
        ((uint2*)(g_Acchi + rowOff))[w2] = ((const uint2*)schi)[w2];
        ((uint2*)(g_Acclo + rowOff))[w2] = ((const uint2*)sclo)[w2];
    }
}

// ---------------- K4: lin: H[b][k][n] (hi/lo bf16) = X @ W ----------------
__global__ __launch_bounds__(256)
void lin_kernel(const float* __restrict__ X, const float* __restrict__ W, int K,
                __nv_bfloat16* __restrict__ Hhi, __nv_bfloat16* __restrict__ Hlo,
                const int* __restrict__ cnt) {
    int b  = blockIdx.x >> 2;
    int rt = blockIdx.x & 3;
    if (cnt && rt * 128 >= cnt[b]) return;   // compact mode: skip empty tiles
    const float* Xb = X + (size_t)(b * NNODE + rt * 128) * K;

    __shared__ float As[8][128];
    __shared__ float Bs[8][128];

    int tid = threadIdx.x;
    int tx = tid & 15, ty = tid >> 4;

    float acc[8][8];
#pragma unroll
    for (int u = 0; u < 8; u++)
#pragma unroll
        for (int v = 0; v < 8; v++) acc[u][v] = 0.f;

    int arow = tid >> 1, acol = (tid & 1) * 4;
    int brow = tid >> 5, bcol = (tid & 31) * 4;

    for (int k0 = 0; k0 < K; k0 += 8) {
        float4 a = *(const float4*)(Xb + (size_t)arow * K + k0 + acol);
        As[acol + 0][arow] = a.x;
        As[acol + 1][arow] = a.y;
        As[acol + 2][arow] = a.z;
        As[acol + 3][arow] = a.w;
        *(float4*)(&Bs[brow][bcol]) = *(const float4*)(W + (size_t)(k0 + brow) * CHID + bcol);
        __syncthreads();
#pragma unroll
        for (int kk = 0; kk < 8; kk++) {
            float ra[8], rb[8];
            *(float4*)(ra)     = *(const float4*)(&As[kk][ty * 8]);
            *(float4*)(ra + 4) = *(const float4*)(&As[kk][ty * 8 + 4]);
            *(float4*)(rb)     = *(const float4*)(&Bs[kk][tx * 8]);
            *(float4*)(rb + 4) = *(const float4*)(&Bs[kk][tx * 8 + 4]);
#pragma unroll
            for (int u = 0; u < 8; u++)
#pragma unroll
                for (int v = 0; v < 8; v++)
                    acc[u][v] = fmaf(ra[u], rb[v], acc[u][v]);
        }
        __syncthreads();
    }

#pragma unroll
    for (int u = 0; u < 8; u++) {
        int row = ty * 8 + u;
        size_t base = ((size_t)(b * NNODE + rt * 128 + row)) * CHID + tx * 8;
        __nv_bfloat16 hi8[8], lo8[8];
#pragma unroll
        for (int v = 0; v < 8; v++) {
            float val = acc[u][v];
            __nv_bfloat16 hi = __float2bfloat16(val);
            hi8[v] = hi;
            lo8[v] = __float2bfloat16(val - __bfloat162float(hi));
        }
        *(uint4*)(Hhi + base) = *(const uint4*)hi8;
        *(uint4*)(Hlo + base) = *(const uint4*)lo8;
    }
}

// ---------------- K5: mma.sync GCN GEMM on compacted rows ----------------
__device__ __forceinline__ void load_chunk(uint32_t st, int c, int tid,
                                           const char* Ah, const char* Al,
                                           const char* Bh, const char* Bl) {
#pragma unroll
    for (int i = 0; i < 2; i++) {
        int item = tid + i * 256;
        int row = item >> 2, seg = item & 3;
        uint32_t so = (uint32_t)(row * ASTR + seg * 16);
        size_t   go = (size_t)row * (NNODE * 2) + (size_t)c * (KC * 2) + seg * 16;
        cp16(st + OFF_AHI + so, Ah + go);
        cp16(st + OFF_ALO + so, Al + go);
    }
#pragma unroll
    for (int i = 0; i < 2; i++) {
        int item = tid + i * 256;
        int kr = item >> 4, seg = item & 15;
        uint32_t so = (uint32_t)(kr * HSTR + seg * 16);
        size_t   go = (size_t)(c * KC + kr) * (CHID * 2) + seg * 16;
        cp16(st + OFF_HHI + so, Bh + go);
        cp16(st + OFF_HLO + so, Bl + go);
    }
    CP_COMMIT();
}

template<bool POOL>
__global__ __launch_bounds__(256, 2)
void gcn_mma_kernel(const __nv_bfloat16* __restrict__ Ahi, const __nv_bfloat16* __restrict__ Alo,
                    const __nv_bfloat16* __restrict__ Hhi, const __nv_bfloat16* __restrict__ Hlo,
                    const float* __restrict__ bias, const int* __restrict__ cntArr,
                    int kfull, float* __restrict__ Hout, float* __restrict__ part) {
    int b = blockIdx.x >> 2, tile = blockIdx.x & 3;
    int cnt = cntArr[b];
    if (tile * 128 >= cnt) return;                       // nothing to compute (part stays 0)
    int nch = kfull ? (NNODE / KC) : ((((cnt + 127) >> 7) << 7) / KC);   // K chunks

    extern __shared__ char smem[];
    uint32_t sb = smem_u32(smem);
    int tid = threadIdx.x;
    int wid = tid >> 5, lane = tid & 31;
    int warpM = wid >> 2, warpN = wid & 3;

    const char* Ah = (const char*)Ahi + ((size_t)(b * NNODE + tile * 128)) * (NNODE * 2);
    const char* Al = (const char*)Alo + ((size_t)(b * NNODE + tile * 128)) * (NNODE * 2);
    const char* Bh = (const char*)Hhi + ((size_t)b * NNODE) * (CHID * 2);
    const char* Bl = (const char*)Hlo + ((size_t)b * NNODE) * (CHID * 2);

    uint32_t aRow = (uint32_t)((warpM * 64 + (lane & 15)) * ASTR + (lane >> 4) * 16);
    uint32_t bRow = (uint32_t)(((lane & 7) + ((lane >> 3) & 1) * 8) * HSTR
                               + (warpN * 32 + ((lane >> 4) & 1) * 8) * 2);

    load_chunk(sb, 0, tid, Ah, Al, Bh, Bl);
    load_chunk(sb + STAGEB, 1, tid, Ah, Al, Bh, Bl);

    float acc[4][4][4];
#pragma unroll
    for (int m = 0; m < 4; m++)
#pragma unroll
        for (int n = 0; n < 4; n++)
#pragma unroll
            for (int k = 0; k < 4; k++) acc[m][n][k] = 0.f;

    int stg = 0;
    for (int c = 0; c < nch; c++) {
        CP_WAIT1();
        __syncthreads();
        int pstg = stg + 2; if (pstg >= NSTG) pstg -= NSTG;
        if (c + 2 < nch)
            load_chunk(sb + (uint32_t)pstg * STAGEB, c + 2, tid, Ah, Al, Bh, Bl);
        else
            CP_COMMIT();
        uint32_t st = sb + (uint32_t)stg * STAGEB;
#pragma unroll
        for (int ks = 0; ks < KC / 16; ks++) {
            uint32_t ahi[4][4], alo[4][4];
#pragma unroll
            for (int mt = 0; mt < 4; mt++) {
                uint32_t ad = st + aRow + (uint32_t)(mt * 16 * ASTR + ks * 32);
                ldm_x4(ahi[mt][0], ahi[mt][1], ahi[mt][2], ahi[mt][3], ad + OFF_AHI);
                ldm_x4(alo[mt][0], alo[mt][1], alo[mt][2], alo[mt][3], ad + OFF_ALO);
            }
            uint32_t bhi[2][4], blo[2][4];
#pragma unroll
            for (int ng = 0; ng < 2; ng++) {
                uint32_t bd = st + bRow + (uint32_t)(ks * 16 * HSTR + ng * 32);
                ldm_x4t(bhi[ng][0], bhi[ng][1], bhi[ng][2], bhi[ng][3], bd + OFF_HHI);
                ldm_x4t(blo[ng][0], blo[ng][1], blo[ng][2], blo[ng][3], bd + OFF_HLO);
            }
#pragma unroll
            for (int mt = 0; mt < 4; mt++)
#pragma unroll
                for (int nt = 0; nt < 4; nt++) {
                    int ng = nt >> 1, hf = nt & 1;
                    mma16816(acc[mt][nt], ahi[mt], bhi[ng][hf * 2], bhi[ng][hf * 2 + 1]);
                    mma16816(acc[mt][nt], ahi[mt], blo[ng][hf * 2], blo[ng][hf * 2 + 1]);
                    mma16816(acc[mt][nt], alo[mt], bhi[ng][hf * 2], bhi[ng][hf * 2 + 1]);
                }
        }
        if (++stg >= NSTG) stg = 0;
    }

    // epilogue: bias + silu; rows >= cnt forced to exact 0 (pad rows)
    int lim = cnt - tile * 128;                     // valid rows in this tile
    int rowBase = b * NNODE + tile * 128 + warpM * 64;
    float* Ob = Hout + (size_t)rowBase * CHID;
    float csum[8];
#pragma unroll
    for (int k = 0; k < 8; k++) csum[k] = 0.f;

#pragma unroll
    for (int mt = 0; mt < 4; mt++) {
        int lr0 = warpM * 64 + mt * 16 + (lane >> 2);   // local row in tile
        bool ok0 = lr0 < lim;
        bool ok1 = (lr0 + 8) < lim;
#pragma unroll
        for (int nt = 0; nt < 4; nt++) {
            int col = warpN * 32 + nt * 8 + (lane & 3) * 2;
            float b0v = bias[col], b1v = bias[col + 1];
            float z0 = ok0 ? (acc[mt][nt][0] + b0v) : 0.f;
            float z1 = ok0 ? (acc[mt][nt][1] + b1v) : 0.f;
            float z2 = ok1 ? (acc[mt][nt][2] + b0v) : 0.f;
            float z3 = ok1 ? (acc[mt][nt][3] + b1v) : 0.f;
            float o0 = z0 / (1.f + __expf(-z0));
            float o1 = z1 / (1.f + __expf(-z1));
            float o2 = z2 / (1.f + __expf(-z2));
            float o3 = z3 / (1.f + __expf(-z3));
            if (POOL) {
                csum[nt * 2]     += o0 + o2;
                csum[nt * 2 + 1] += o1 + o3;
            } else {
                int r0 = mt * 16 + (lane >> 2);
                *(float2*)(Ob + (size_t)r0 * CHID + col)       = make_float2(o0, o1);
                *(float2*)(Ob + (size_t)(r0 + 8) * CHID + col) = make_float2(o2, o3);
            }
        }
    }

    if (POOL) {
        __shared__ float spool[2][CHID];
#pragma unroll
        for (int off = 4; off < 32; off <<= 1)
#pragma unroll
            for (int k = 0; k < 8; k++)
                csum[k] += __shfl_xor_sync(0xffffffffu, csum[k], off);
        if ((lane >> 2) == 0) {
#pragma unroll
            for (int nt = 0; nt < 4; nt++) {
                int col = warpN * 32 + nt * 8 + (lane & 3) * 2;
                spool[warpM][col]     = csum[nt * 2];
                spool[warpM][col + 1] = csum[nt * 2 + 1];
            }
        }
        __syncthreads();
        if (tid < CHID)
            part[(b * 4 + tile) * CHID + tid] = spool[0][tid] + spool[1][tid];
    }
}

// ---------------- K6: head from pooled partials ----------------
__global__ void head_kernel(const float* __restrict__ part,
                            const float* __restrict__ Wl1, const float* __restrict__ bl1,
                            const float* __restrict__ Wl2, const float* __restrict__ bl2,
                            float* __restrict__ out) {
    int b = blockIdx.x;
    int c = threadIdx.x;     // 128 threads
    __shared__ float g[CHID], g1[CHID];
    const float* pb = part + b * 4 * CHID;
    g[c] = (pb[c] + pb[CHID + c] + pb[2 * CHID + c] + pb[3 * CHID + c]) * (1.0f / NNODE);
    __syncthreads();
    float acc = bl1[c];
    for (int k = 0; k < CHID; k++) acc = fmaf(g[k], Wl1[k * CHID + c], acc);
    g1[c] = acc / (1.f + __expf(-acc));
    __syncthreads();
    if (c < COUT) {
        float acc2 = bl2[c];
        for (int k = 0; k < CHID; k++) acc2 = fmaf(g1[k], Wl2[k * COUT + c], acc2);
        out[b * COUT + c] = acc2;
    }
}

// ---------------- launch ----------------
extern "C" void kernel_launch(void* const* d_in, const int* in_sizes, int n_in,
                              void* d_out, int out_size) {
    const float* x    = (const float*)d_in[0];
    const float* adj  = (const float*)d_in[1];
    const int*   mask = (const int*)  d_in[2];
    const float* W0   = (const float*)d_in[3];
    const float* b0   = (const float*)d_in[4];
    const float* W1   = (const float*)d_in[5];
    const float* b1   = (const float*)d_in[6];
    const float* Wl1  = (const float*)d_in[7];
    const float* bl1  = (const float*)d_in[8];
    const float* Wl2  = (const float*)d_in[9];
    const float* bl2  = (const float*)d_in[10];
    float* out = (float*)d_out;

    __nv_bfloat16 *dAchi, *dAclo, *dAcchi, *dAcclo, *dHhi, *dHlo;
    float *dHout, *dPart;
    int *dCnt;
    cudaGetSymbolAddress((void**)&dAchi,  g_Achi);
    cudaGetSymbolAddress((void**)&dAclo,  g_Aclo);
    cudaGetSymbolAddress((void**)&dAcchi, g_Acchi);
    cudaGetSymbolAddress((void**)&dAcclo, g_Acclo);
    cudaGetSymbolAddress((void**)&dHhi,   g_Hhi);
    cudaGetSymbolAddress((void**)&dHlo,   g_Hlo);
    cudaGetSymbolAddress((void**)&dHout,  g_hout);
    cudaGetSymbolAddress((void**)&dPart,  g_part);
    cudaGetSymbolAddress((void**)&dCnt,   g_cnt);

    static int smem_set = 0;
    if (!smem_set) {
        cudaFuncSetAttribute(gcn_mma_kernel<false>,
                             cudaFuncAttributeMaxDynamicSharedMemorySize, SMEM_DYN);
        cudaFuncSetAttribute(gcn_mma_kernel<true>,
                             cudaFuncAttributeMaxDynamicSharedMemorySize, SMEM_DYN);
        smem_set = 1;
    }

    // 1) degrees (full pass: normalization needs all nodes)
    deg_kernel<<<BATCH * NNODE, 128>>>(adj);
    // 2) mask compaction (idx, cnt)
    compact_kernel<<<BATCH, NNODE>>>(mask);
    // 3) compacted normalized adjacency: Ac (rows compact) + Acc (rows+cols compact)
    buildA_kernel<<<BATCH * NNODE, 128>>>(adj);
    // 4) H = x @ W0 (dense, all nodes feed layer-1 K)
    lin_kernel<<<BATCH * 4, 256>>>(x, W0, CIN, dHhi, dHlo, nullptr);
    // 5) layer 1: compact rows, full K=512
    gcn_mma_kernel<false><<<BATCH * 4, 256, SMEM_DYN>>>(dAchi, dAclo, dHhi, dHlo, b0,
                                                        dCnt, 1, dHout, dPart);
    // 6) Hc = h1c @ W1 (compact rows)
    lin_kernel<<<BATCH * 4, 256>>>(dHout, W1, CHID, dHhi, dHlo, dCnt);
    // 7) layer 2: compact rows AND compact K, fused mean-pool
    gcn_mma_kernel<true><<<BATCH * 4, 256, SMEM_DYN>>>(dAcchi, dAcclo, dHhi, dHlo, b1,
                                                       dCnt, 0, dHout, dPart);
    // 8) MLP head
    head_kernel<<<BATCH, CHID>>>(dPart, Wl1, bl1, Wl2, bl2, out);
}

// round 13
// speedup vs baseline: 1.0058x; 1.0047x over previous
#include <cuda_runtime.h>
#include <cuda_bf16.h>
#include <cstdint>
#include <math.h>

#define BATCH 64
#define NNODE 512
#define NEDGE 4
#define CIN   64
#define CHID  128
#define COUT  16

// ---- mma.sync GEMM tiling ----
#define KC 32                               // K per pipeline chunk
#define NSTG 3                              // pipeline stages
#define ASTR 80                             // A smem row stride bytes (32 bf16 + 16 pad)
#define HSTR 272                            // H smem row stride bytes (128 bf16 + 8 pad)
#define OFF_AHI 0
#define OFF_ALO (128 * ASTR)                // 10240
#define OFF_HHI (2 * 128 * ASTR)            // 20480
#define OFF_HLO (2 * 128 * ASTR + KC * HSTR)
#define STAGEB  (2 * 128 * ASTR + 2 * KC * HSTR)   // 37888
#define SMEM_DYN (NSTG * STAGEB)                    // 113664 -> 2 CTAs/SM

// ---------------- device scratch (zero-initialized at module load) ----------------
__device__ float          g_deg  [BATCH * NNODE * NEDGE];
__device__ int            g_idx  [BATCH * NNODE];                   // compact slot -> node
__device__ int            g_cnt  [BATCH];                           // masked-node count
__device__ __nv_bfloat16  g_Achi [(size_t)BATCH * NNODE * NNODE];   // rows compact, cols full
__device__ __nv_bfloat16  g_Aclo [(size_t)BATCH * NNODE * NNODE];
__device__ __nv_bfloat16  g_Acchi[(size_t)BATCH * NNODE * NNODE];   // rows+cols compact
__device__ __nv_bfloat16  g_Acclo[(size_t)BATCH * NNODE * NNODE];
__device__ __nv_bfloat16  g_Hhi  [(size_t)BATCH * NNODE * CHID];    // [b][k][n]
__device__ __nv_bfloat16  g_Hlo  [(size_t)BATCH * NNODE * CHID];
__device__ float          g_hout [(size_t)BATCH * NNODE * CHID];    // layer-1 out (compact rows)
__device__ float          g_part [BATCH * 4 * CHID];                // pooled partials

// ---------------- PTX helpers ----------------
__device__ __forceinline__ uint32_t smem_u32(const void* p) {
    uint32_t a;
    asm("{ .reg .u64 t; cvta.to.shared.u64 t, %1; cvt.u32.u64 %0, t; }" : "=r"(a) : "l"(p));
    return a;
}
__device__ __forceinline__ void cp16(uint32_t dst, const void* src) {
    asm volatile("cp.async.cg.shared.global [%0], [%1], 16;" :: "r"(dst), "l"(src));
}
#define CP_COMMIT() asm volatile("cp.async.commit_group;" ::: "memory")
#define CP_WAIT1()  asm volatile("cp.async.wait_group 1;"  ::: "memory")

__device__ __forceinline__ void ldm_x4(uint32_t& r0, uint32_t& r1, uint32_t& r2, uint32_t& r3,
                                       uint32_t a) {
    asm volatile("ldmatrix.sync.aligned.m8n8.x4.shared.b16 {%0,%1,%2,%3}, [%4];"
                 : "=r"(r0), "=r"(r1), "=r"(r2), "=r"(r3) : "r"(a));
}
__device__ __forceinline__ void ldm_x4t(uint32_t& r0, uint32_t& r1, uint32_t& r2, uint32_t& r3,
                                        uint32_t a) {
    asm volatile("ldmatrix.sync.aligned.m8n8.x4.trans.shared.b16 {%0,%1,%2,%3}, [%4];"
                 : "=r"(r0), "=r"(r1), "=r"(r2), "=r"(r3) : "r"(a));
}
__device__ __forceinline__ void mma16816(float* c, const uint32_t* a, uint32_t b0, uint32_t b1) {
    asm volatile(
        "mma.sync.aligned.m16n8k16.row.col.f32.bf16.bf16.f32 "
        "{%0,%1,%2,%3}, {%4,%5,%6,%7}, {%8,%9}, {%0,%1,%2,%3};"
        : "+f"(c[0]), "+f"(c[1]), "+f"(c[2]), "+f"(c[3])
        : "r"(a[0]), "r"(a[1]), "r"(a[2]), "r"(a[3]), "r"(b0), "r"(b1));
}

// ---------------- K1: degrees -> rsqrt(max(sum,1)) ----------------
__global__ void deg_kernel(const float* __restrict__ adj) {
    int bi = blockIdx.x;
    int i  = bi & (NNODE - 1);
    const float4* row = (const float4*)(adj + (size_t)bi * (NNODE * NEDGE));
    int j = threadIdx.x;
    float4 v0 = row[j];
    float4 v1 = row[j + 128];
    float4 v2 = row[j + 256];
    float4 v3 = row[j + 384];
    if (j == i)         v0 = make_float4(1.f, 1.f, 1.f, 1.f);
    if (j + 128 == i)   v1 = make_float4(1.f, 1.f, 1.f, 1.f);
    if (j + 256 == i)   v2 = make_float4(1.f, 1.f, 1.f, 1.f);
    if (j + 384 == i)   v3 = make_float4(1.f, 1.f, 1.f, 1.f);
    float4 s;
    s.x = (v0.x + v1.x) + (v2.x + v3.x);
    s.y = (v0.y + v1.y) + (v2.y + v3.y);
    s.z = (v0.z + v1.z) + (v2.z + v3.z);
    s.w = (v0.w + v1.w) + (v2.w + v3.w);
    for (int o = 16; o > 0; o >>= 1) {
        s.x += __shfl_down_sync(0xffffffffu, s.x, o);
        s.y += __shfl_down_sync(0xffffffffu, s.y, o);
        s.z += __shfl_down_sync(0xffffffffu, s.z, o);
        s.w += __shfl_down_sync(0xffffffffu, s.w, o);
    }
    __shared__ float4 sh[4];
    int lane = threadIdx.x & 31, w = threadIdx.x >> 5;
    if (lane == 0) sh[w] = s;
    __syncthreads();
    if (threadIdx.x == 0) {
        float4 t = sh[0];
        t.x += sh[1].x + sh[2].x + sh[3].x;
        t.y += sh[1].y + sh[2].y + sh[3].y;
        t.z += sh[1].z + sh[2].z + sh[3].z;
        t.w += sh[1].w + sh[2].w + sh[3].w;
        float4 r;
        r.x = rsqrtf(fmaxf(t.x, 1.f));
        r.y = rsqrtf(fmaxf(t.y, 1.f));
        r.z = rsqrtf(fmaxf(t.z, 1.f));
        r.w = rsqrtf(fmaxf(t.w, 1.f));
        ((float4*)g_deg)[bi] = r;
    }
}

// ---------------- K2: deterministic mask compaction ----------------
__global__ void compact_kernel(const int* __restrict__ mask) {
    __shared__ int woff[17];
    int b = blockIdx.x, t = threadIdx.x, lane = t & 31, w = t >> 5;
    int m = mask[b * NNODE + t];
    unsigned bal = __ballot_sync(0xffffffffu, m != 0);
    if (lane == 0) woff[w + 1] = __popc(bal);
    if (t == 0) woff[0] = 0;
    __syncthreads();
    if (t == 0) for (int k = 1; k <= 16; k++) woff[k] += woff[k - 1];
    __syncthreads();
    if (m) {
        int rank = woff[w] + __popc(bal & ((1u << lane) - 1u));
        g_idx[b * NNODE + rank] = t;
    }
    if (t == 0) g_cnt[b] = woff[16];
}

// ---------------- K3: build compacted normalized adjacency (Ac + Acc) ----------------
// one CTA (128 thr) per (b, compact row ri); reads only masked adj rows
__global__ __launch_bounds__(128)
void buildA_kernel(const float* __restrict__ adj) {
    int blk = blockIdx.x;
    int b = blk >> 9, ri = blk & (NNODE - 1);
    int cnt = g_cnt[b];
    if (ri >= cnt) return;
    int i = g_idx[b * NNODE + ri];
    int t = threadIdx.x;

    const float4* row = (const float4*)(adj + ((size_t)(b * NNODE + i)) * (NNODE * NEDGE));
    float4 di = ((const float4*)g_deg)[b * NNODE + i];

    __shared__ __nv_bfloat16 shi[NNODE], slo[NNODE];
    __shared__ __nv_bfloat16 schi[NNODE], sclo[NNODE];

#pragma unroll
    for (int q = 0; q < 4; q++) {
        int j = t + q * 128;
        float4 a = row[j];
        if (j == i) a = make_float4(1.f, 1.f, 1.f, 1.f);
        float4 dj = ((const float4*)g_deg)[b * NNODE + j];
        float v = a.x * di.x * dj.x + a.y * di.y * dj.y + a.z * di.z * dj.z + a.w * di.w * dj.w;
        __nv_bfloat16 hi = __float2bfloat16(v);
        shi[j] = hi;
        slo[j] = __float2bfloat16(v - __bfloat162float(hi));
    }
    __syncthreads();

    size_t rowOff = ((size_t)(b * NNODE + ri)) * NNODE;
    // Ac: full 512 cols, vector copy from smem (1KB per array)
    ((uint2*)(g_Achi + rowOff))[t] = ((const uint2*)shi)[t];
    ((uint2*)(g_Aclo + rowOff))[t] = ((const uint2*)slo)[t];

    // Acc: gather masked cols into compact order
    for (int rj = t; rj < cnt; rj += 128) {
        int j = g_idx[b * NNODE + rj];
        schi[rj] = shi[j];
        sclo[rj] = slo[j];
    }
    // zero tail up to 8B boundary
    int cntPad = (cnt + 3) & ~3;
    for (int rj = cnt + t; rj < cntPad; rj += 128) { schi[rj] = __float2bfloat16(0.f); sclo[rj] = __float2bfloat16(0.f); }
    __syncthreads();
    int nW = cntPad >> 2;   // uint2 count (4 bf16 each)
    for (int w2 = t; w2 < nW; w2 += 128) {
        ((uint2*)(g_Acchi + rowOff))[w2] = ((const uint2*)schi)[w2];
        ((uint2*)(g_Acclo + rowOff))[w2] = ((const uint2*)sclo)[w2];
    }
}

// ---------------- K4: lin: H[b][k][n] (hi/lo bf16) = X @ W ----------------
__global__ __launch_bounds__(256)
void lin_kernel(const float* __restrict__ X, const float* __restrict__ W, int K,
                __nv_bfloat16* __restrict__ Hhi, __nv_bfloat16* __restrict__ Hlo,
                const int* __restrict__ cnt) {
    int b  = blockIdx.x >> 2;
    int rt = blockIdx.x & 3;
    if (cnt && rt * 128 >= cnt[b]) return;   // compact mode: skip empty tiles
    const float* Xb = X + (size_t)(b * NNODE + rt * 128) * K;

    __shared__ float As[8][128];
    __shared__ float Bs[8][128];

    int tid = threadIdx.x;
    int tx = tid & 15, ty = tid >> 4;

    float acc[8][8];
#pragma unroll
    for (int u = 0; u < 8; u++)
#pragma unroll
        for (int v = 0; v < 8; v++) acc[u][v] = 0.f;

    int arow = tid >> 1, acol = (tid & 1) * 4;
    int brow = tid >> 5, bcol = (tid & 31) * 4;

    for (int k0 = 0; k0 < K; k0 += 8) {
        float4 a = *(const float4*)(Xb + (size_t)arow * K + k0 + acol);
        As[acol + 0][arow] = a.x;
        As[acol + 1][arow] = a.y;
        As[acol + 2][arow] = a.z;
        As[acol + 3][arow] = a.w;
        *(float4*)(&Bs[brow][bcol]) = *(const float4*)(W + (size_t)(k0 + brow) * CHID + bcol);
        __syncthreads();
#pragma unroll
        for (int kk = 0; kk < 8; kk++) {
            float ra[8], rb[8];
            *(float4*)(ra)     = *(const float4*)(&As[kk][ty * 8]);
            *(float4*)(ra + 4) = *(const float4*)(&As[kk][ty * 8 + 4]);
            *(float4*)(rb)     = *(const float4*)(&Bs[kk][tx * 8]);
            *(float4*)(rb + 4) = *(const float4*)(&Bs[kk][tx * 8 + 4]);
#pragma unroll
            for (int u = 0; u < 8; u++)
#pragma unroll
                for (int v = 0; v < 8; v++)
                    acc[u][v] = fmaf(ra[u], rb[v], acc[u][v]);
        }
        __syncthreads();
    }

#pragma unroll
    for (int u = 0; u < 8; u++) {
        int row = ty * 8 + u;
        size_t base = ((size_t)(b * NNODE + rt * 128 + row)) * CHID + tx * 8;
        __nv_bfloat16 hi8[8], lo8[8];
#pragma unroll
        for (int v = 0; v < 8; v++) {
            float val = acc[u][v];
            __nv_bfloat16 hi = __float2bfloat16(val);
            hi8[v] = hi;
            lo8[v] = __float2bfloat16(val - __bfloat162float(hi));
        }
        *(uint4*)(Hhi + base) = *(const uint4*)hi8;
        *(uint4*)(Hlo + base) = *(const uint4*)lo8;
    }
}

// ---------------- K5: mma.sync GCN GEMM on compacted rows ----------------
__device__ __forceinline__ void load_chunk(uint32_t st, int c, int tid,
                                           const char* Ah, const char* Al,
                                           const char* Bh, const char* Bl) {
#pragma unroll
    for (int i = 0; i < 2; i++) {
        int item = tid + i * 256;
        int row = item >> 2, seg = item & 3;
        uint32_t so = (uint32_t)(row * ASTR + seg * 16);
        size_t   go = (size_t)row * (NNODE * 2) + (size_t)c * (KC * 2) + seg * 16;
        cp16(st + OFF_AHI + so, Ah + go);
        cp16(st + OFF_ALO + so, Al + go);
    }
#pragma unroll
    for (int i = 0; i < 2; i++) {
        int item = tid + i * 256;
        int kr = item >> 4, seg = item & 15;
        uint32_t so = (uint32_t)(kr * HSTR + seg * 16);
        size_t   go = (size_t)(c * KC + kr) * (CHID * 2) + seg * 16;
        cp16(st + OFF_HHI + so, Bh + go);
        cp16(st + OFF_HLO + so, Bl + go);
    }
    CP_COMMIT();
}

template<bool POOL>
__global__ __launch_bounds__(256, 2)
void gcn_mma_kernel(const __nv_bfloat16* __restrict__ Ahi, const __nv_bfloat16* __restrict__ Alo,
                    const __nv_bfloat16* __restrict__ Hhi, const __nv_bfloat16* __restrict__ Hlo,
                    const float* __restrict__ bias, const int* __restrict__ cntArr,
                    int kfull, float* __restrict__ Hout, float* __restrict__ part) {
    int b = blockIdx.x >> 2, tile = blockIdx.x & 3;
    int cnt = cntArr[b];
    if (tile * 128 >= cnt) return;                       // nothing to compute (part stays 0)
    int nch = kfull ? (NNODE / KC) : ((((cnt + 127) >> 7) << 7) / KC);   // K chunks

    extern __shared__ char smem[];
    uint32_t sb = smem_u32(smem);
    int tid = threadIdx.x;
    int wid = tid >> 5, lane = tid & 31;
    int warpM = wid >> 2, warpN = wid & 3;

    const char* Ah = (const char*)Ahi + ((size_t)(b * NNODE + tile * 128)) * (NNODE * 2);
    const char* Al = (const char*)Alo + ((size_t)(b * NNODE + tile * 128)) * (NNODE * 2);
    const char* Bh = (const char*)Hhi + ((size_t)b * NNODE) * (CHID * 2);
    const char* Bl = (const char*)Hlo + ((size_t)b * NNODE) * (CHID * 2);

    uint32_t aRow = (uint32_t)((warpM * 64 + (lane & 15)) * ASTR + (lane >> 4) * 16);
    uint32_t bRow = (uint32_t)(((lane & 7) + ((lane >> 3) & 1) * 8) * HSTR
                               + (warpN * 32 + ((lane >> 4) & 1) * 8) * 2);

    load_chunk(sb, 0, tid, Ah, Al, Bh, Bl);
    load_chunk(sb + STAGEB, 1, tid, Ah, Al, Bh, Bl);

    float acc[4][4][4];
#pragma unroll
    for (int m = 0; m < 4; m++)
#pragma unroll
        for (int n = 0; n < 4; n++)
#pragma unroll
            for (int k = 0; k < 4; k++) acc[m][n][k] = 0.f;

    int stg = 0;
    for (int c = 0; c < nch; c++) {
        CP_WAIT1();
        __syncthreads();
        int pstg = stg + 2; if (pstg >= NSTG) pstg -= NSTG;
        if (c + 2 < nch)
            load_chunk(sb + (uint32_t)pstg * STAGEB, c + 2, tid, Ah, Al, Bh, Bl);
        else
            CP_COMMIT();
        uint32_t st = sb + (uint32_t)stg * STAGEB;
#pragma unroll
        for (int ks = 0; ks < KC / 16; ks++) {
            uint32_t ahi[4][4], alo[4][4];
#pragma unroll
            for (int mt = 0; mt < 4; mt++) {
                uint32_t ad = st + aRow + (uint32_t)(mt * 16 * ASTR + ks * 32);
                ldm_x4(ahi[mt][0], ahi[mt][1], ahi[mt][2], ahi[mt][3], ad + OFF_AHI);
                ldm_x4(alo[mt][0], alo[mt][1], alo[mt][2], alo[mt][3], ad + OFF_ALO);
            }
            uint32_t bhi[2][4], blo[2][4];
#pragma unroll
            for (int ng = 0; ng < 2; ng++) {
                uint32_t bd = st + bRow + (uint32_t)(ks * 16 * HSTR + ng * 32);
                ldm_x4t(bhi[ng][0], bhi[ng][1], bhi[ng][2], bhi[ng][3], bd + OFF_HHI);
                ldm_x4t(blo[ng][0], blo[ng][1], blo[ng][2], blo[ng][3], bd + OFF_HLO);
            }
#pragma unroll
            for (int mt = 0; mt < 4; mt++)
#pragma unroll
                for (int nt = 0; nt < 4; nt++) {
                    int ng = nt >> 1, hf = nt & 1;
                    mma16816(acc[mt][nt], ahi[mt], bhi[ng][hf * 2], bhi[ng][hf * 2 + 1]);
                    mma16816(acc[mt][nt], ahi[mt], blo[ng][hf * 2], blo[ng][hf * 2 + 1]);
                    mma16816(acc[mt][nt], alo[mt], bhi[ng][hf * 2], bhi[ng][hf * 2 + 1]);
                }
        }
        if (++stg >= NSTG) stg = 0;
    }

    // epilogue: bias + silu; rows >= cnt forced to exact 0 (pad rows)
    int lim = cnt - tile * 128;                     // valid rows in this tile
    int rowBase = b * NNODE + tile * 128 + warpM * 64;
    float* Ob = Hout + (size_t)rowBase * CHID;
    float csum[8];
#pragma unroll
    for (int k = 0; k < 8; k++) csum[k] = 0.f;

#pragma unroll
    for (int mt = 0; mt < 4; mt++) {
        int lr0 = warpM * 64 + mt * 16 + (lane >> 2);   // local row in tile
        bool ok0 = lr0 < lim;
        bool ok1 = (lr0 + 8) < lim;
#pragma unroll
        for (int nt = 0; nt < 4; nt++) {
            int col = warpN * 32 + nt * 8 + (lane & 3) * 2;
            float b0v = bias[col], b1v = bias[col + 1];
            float z0 = ok0 ? (acc[mt][nt][0] + b0v) : 0.f;
            float z1 = ok0 ? (acc[mt][nt][1] + b1v) : 0.f;
            float z2 = ok1 ? (acc[mt][nt][2] + b0v) : 0.f;
            float z3 = ok1 ? (acc[mt][nt][3] + b1v) : 0.f;
            float o0 = z0 / (1.f + __expf(-z0));
            float o1 = z1 / (1.f + __expf(-z1));
            float o2 = z2 / (1.f + __expf(-z2));
            float o3 = z3 / (1.f + __expf(-z3));
            if (POOL) {
                csum[nt * 2]     += o0 + o2;
                csum[nt * 2 + 1] += o1 + o3;
            } else {
                int r0 = mt * 16 + (lane >> 2);
                *(float2*)(Ob + (size_t)r0 * CHID + col)       = make_float2(o0, o1);
                *(float2*)(Ob + (size_t)(r0 + 8) * CHID + col) = make_float2(o2, o3);
            }
        }
    }

    if (POOL) {
        __shared__ float spool[2][CHID];
#pragma unroll
        for (int off = 4; off < 32; off <<= 1)
#pragma unroll
            for (int k = 0; k < 8; k++)
                csum[k] += __shfl_xor_sync(0xffffffffu, csum[k], off);
        if ((lane >> 2) == 0) {
#pragma unroll
            for (int nt = 0; nt < 4; nt++) {
                int col = warpN * 32 + nt * 8 + (lane & 3) * 2;
                spool[warpM][col]     = csum[nt * 2];
                spool[warpM][col + 1] = csum[nt * 2 + 1];
            }
        }
        __syncthreads();
        if (tid < CHID)
            part[(b * 4 + tile) * CHID + tid] = spool[0][tid] + spool[1][tid];
    }
}

// ---------------- K6: head from pooled partials ----------------
__global__ void head_kernel(const float* __restrict__ part,
                            const float* __restrict__ Wl1, const float* __restrict__ bl1,
                            const float* __restrict__ Wl2, const float* __restrict__ bl2,
                            float* __restrict__ out) {
    int b = blockIdx.x;
    int c = threadIdx.x;     // 128 threads
    __shared__ float g[CHID], g1[CHID];
    const float* pb = part + b * 4 * CHID;
    g[c] = (pb[c] + pb[CHID + c] + pb[2 * CHID + c] + pb[3 * CHID + c]) * (1.0f / NNODE);
    __syncthreads();
    float acc = bl1[c];
    for (int k = 0; k < CHID; k++) acc = fmaf(g[k], Wl1[k * CHID + c], acc);
    g1[c] = acc / (1.f + __expf(-acc));
    __syncthreads();
    if (c < COUT) {
        float acc2 = bl2[c];
        for (int k = 0; k < CHID; k++) acc2 = fmaf(g1[k], Wl2[k * COUT + c], acc2);
        out[b * COUT + c] = acc2;
    }
}

// ---------------- launch ----------------
extern "C" void kernel_launch(void* const* d_in, const int* in_sizes, int n_in,
                              void* d_out, int out_size) {
    const float* x    = (const float*)d_in[0];
    const float* adj  = (const float*)d_in[1];
    const int*   mask = (const int*)  d_in[2];
    const float* W0   = (const float*)d_in[3];
    const float* b0   = (const float*)d_in[4];
    const float* W1   = (const float*)d_in[5];
    const float* b1   = (const float*)d_in[6];
    const float* Wl1  = (const float*)d_in[7];
    const float* bl1  = (const float*)d_in[8];
    const float* Wl2  = (const float*)d_in[9];
    const float* bl2  = (const float*)d_in[10];
    float* out = (float*)d_out;

    __nv_bfloat16 *dAchi, *dAclo, *dAcchi, *dAcclo, *dHhi, *dHlo;
    float *dHout, *dPart;
    int *dCnt;
    cudaGetSymbolAddress((void**)&dAchi,  g_Achi);
    cudaGetSymbolAddress((void**)&dAclo,  g_Aclo);
    cudaGetSymbolAddress((void**)&dAcchi, g_Acchi);
    cudaGetSymbolAddress((void**)&dAcclo, g_Acclo);
    cudaGetSymbolAddress((void**)&dHhi,   g_Hhi);
    cudaGetSymbolAddress((void**)&dHlo,   g_Hlo);
    cudaGetSymbolAddress((void**)&dHout,  g_hout);
    cudaGetSymbolAddress((void**)&dPart,  g_part);
    cudaGetSymbolAddress((void**)&dCnt,   g_cnt);

    static int smem_set = 0;
    if (!smem_set) {
        cudaFuncSetAttribute(gcn_mma_kernel<false>,
                             cudaFuncAttributeMaxDynamicSharedMemorySize, SMEM_DYN);
        cudaFuncSetAttribute(gcn_mma_kernel<true>,
                             cudaFuncAttributeMaxDynamicSharedMemorySize, SMEM_DYN);
        smem_set = 1;
    }

    // 1) degrees (full pass: normalization needs all nodes)
    deg_kernel<<<BATCH * NNODE, 128>>>(adj);
    // 2) mask compaction (idx, cnt)
    compact_kernel<<<BATCH, NNODE>>>(mask);
    // 3) compacted normalized adjacency: Ac (rows compact) + Acc (rows+cols compact)
    buildA_kernel<<<BATCH * NNODE, 128>>>(adj);
    // 4) H = x @ W0 (dense, all nodes feed layer-1 K)
    lin_kernel<<<BATCH * 4, 256>>>(x, W0, CIN, dHhi, dHlo, nullptr);
    // 5) layer 1: compact rows, full K=512
    gcn_mma_kernel<false><<<BATCH * 4, 256, SMEM_DYN>>>(dAchi, dAclo, dHhi, dHlo, b0,
                                                        dCnt, 1, dHout, dPart);
    // 6) Hc = h1c @ W1 (compact rows)
    lin_kernel<<<BATCH * 4, 256>>>(dHout, W1, CHID, dHhi, dHlo, dCnt);
    // 7) layer 2: compact rows AND compact K, fused mean-pool
    gcn_mma_kernel<true><<<BATCH * 4, 256, SMEM_DYN>>>(dAcchi, dAcclo, dHhi, dHlo, b1,
                                                       dCnt, 0, dHout, dPart);
    // 8) MLP head
    head_kernel<<<BATCH, CHID>>>(dPart, Wl1, bl1, Wl2, bl2, out);
}

// round 14
// speedup vs baseline: 1.0070x; 1.0012x over previous
#include <cuda_runtime.h>
#include <cuda_bf16.h>
#include <cstdint>
#include <math.h>

#define BATCH 64
#define NNODE 512
#define NEDGE 4
#define CIN   64
#define CHID  128
#define COUT  16

// ---- mma.sync GEMM tiling ----
#define KC 32                               // K per pipeline chunk
#define NSTG 3                              // pipeline stages
#define ASTR 80                             // A smem row stride bytes (32 bf16 + 16 pad)
#define HSTR 272                            // H smem row stride bytes (128 bf16 + 8 pad)
#define OFF_AHI 0
#define OFF_ALO (128 * ASTR)                // 10240
#define OFF_HHI (2 * 128 * ASTR)            // 20480
#define OFF_HLO (2 * 128 * ASTR + KC * HSTR)
#define STAGEB  (2 * 128 * ASTR + 2 * KC * HSTR)   // 37888
#define SMEM_DYN (NSTG * STAGEB)                    // 113664 -> 2 CTAs/SM

// ---------------- device scratch (zero-initialized at module load) ----------------
__device__ float          g_deg  [BATCH * NNODE * NEDGE];
__device__ int            g_idx  [BATCH * NNODE];                   // compact slot -> node
__device__ int            g_cnt  [BATCH];                           // masked-node count
__device__ __nv_bfloat16  g_Achi [(size_t)BATCH * NNODE * NNODE];   // rows compact, cols full
__device__ __nv_bfloat16  g_Aclo [(size_t)BATCH * NNODE * NNODE];
__device__ __nv_bfloat16  g_Acchi[(size_t)BATCH * NNODE * NNODE];   // rows+cols compact
__device__ __nv_bfloat16  g_Acclo[(size_t)BATCH * NNODE * NNODE];
__device__ __nv_bfloat16  g_Hhi  [(size_t)BATCH * NNODE * CHID];    // [b][k][n]
__device__ __nv_bfloat16  g_Hlo  [(size_t)BATCH * NNODE * CHID];
__device__ float          g_hout [(size_t)BATCH * NNODE * CHID];    // layer-1 out (compact rows)
__device__ float          g_part [BATCH * 4 * CHID];                // pooled partials

// ---------------- PTX helpers ----------------
__device__ __forceinline__ uint32_t smem_u32(const void* p) {
    uint32_t a;
    asm("{ .reg .u64 t; cvta.to.shared.u64 t, %1; cvt.u32.u64 %0, t; }" : "=r"(a) : "l"(p));
    return a;
}
__device__ __forceinline__ void cp16(uint32_t dst, const void* src) {
    asm volatile("cp.async.cg.shared.global [%0], [%1], 16;" :: "r"(dst), "l"(src));
}
#define CP_COMMIT() asm volatile("cp.async.commit_group;" ::: "memory")
#define CP_WAIT1()  asm volatile("cp.async.wait_group 1;"  ::: "memory")

__device__ __forceinline__ void ldm_x4(uint32_t& r0, uint32_t& r1, uint32_t& r2, uint32_t& r3,
                                       uint32_t a) {
    asm volatile("ldmatrix.sync.aligned.m8n8.x4.shared.b16 {%0,%1,%2,%3}, [%4];"
                 : "=r"(r0), "=r"(r1), "=r"(r2), "=r"(r3) : "r"(a));
}
__device__ __forceinline__ void ldm_x4t(uint32_t& r0, uint32_t& r1, uint32_t& r2, uint32_t& r3,
                                        uint32_t a) {
    asm volatile("ldmatrix.sync.aligned.m8n8.x4.trans.shared.b16 {%0,%1,%2,%3}, [%4];"
                 : "=r"(r0), "=r"(r1), "=r"(r2), "=r"(r3) : "r"(a));
}
__device__ __forceinline__ void mma16816(float* c, const uint32_t* a, uint32_t b0, uint32_t b1) {
    asm volatile(
        "mma.sync.aligned.m16n8k16.row.col.f32.bf16.bf16.f32 "
        "{%0,%1,%2,%3}, {%4,%5,%6,%7}, {%8,%9}, {%0,%1,%2,%3};"
        : "+f"(c[0]), "+f"(c[1]), "+f"(c[2]), "+f"(c[3])
        : "r"(a[0]), "r"(a[1]), "r"(a[2]), "r"(a[3]), "r"(b0), "r"(b1));
}

// ---------------- K1: degrees -> rsqrt(max(sum,1)) ----------------
__global__ void deg_kernel(const float* __restrict__ adj) {
    int bi = blockIdx.x;
    int i  = bi & (NNODE - 1);
    const float4* row = (const float4*)(adj + (size_t)bi * (NNODE * NEDGE));
    int j = threadIdx.x;
    float4 v0 = row[j];
    float4 v1 = row[j + 128];
    float4 v2 = row[j + 256];
    float4 v3 = row[j + 384];
    if (j == i)         v0 = make_float4(1.f, 1.f, 1.f, 1.f);
    if (j + 128 == i)   v1 = make_float4(1.f, 1.f, 1.f, 1.f);
    if (j + 256 == i)   v2 = make_float4(1.f, 1.f, 1.f, 1.f);
    if (j + 384 == i)   v3 = make_float4(1.f, 1.f, 1.f, 1.f);
    float4 s;
    s.x = (v0.x + v1.x) + (v2.x + v3.x);
    s.y = (v0.y + v1.y) + (v2.y + v3.y);
    s.z = (v0.z + v1.z) + (v2.z + v3.z);
    s.w = (v0.w + v1.w) + (v2.w + v3.w);
    for (int o = 16; o > 0; o >>= 1) {
        s.x += __shfl_down_sync(0xffffffffu, s.x, o);
        s.y += __shfl_down_sync(0xffffffffu, s.y, o);
        s.z += __shfl_down_sync(0xffffffffu, s.z, o);
        s.w += __shfl_down_sync(0xffffffffu, s.w, o);
    }
    __shared__ float4 sh[4];
    int lane = threadIdx.x & 31, w = threadIdx.x >> 5;
    if (lane == 0) sh[w] = s;
    __syncthreads();
    if (threadIdx.x == 0) {
        float4 t = sh[0];
        t.x += sh[1].x + sh[2].x + sh[3].x;
        t.y += sh[1].y + sh[2].y + sh[3].y;
        t.z += sh[1].z + sh[2].z + sh[3].z;
        t.w += sh[1].w + sh[2].w + sh[3].w;
        float4 r;
        r.x = rsqrtf(fmaxf(t.x, 1.f));
        r.y = rsqrtf(fmaxf(t.y, 1.f));
        r.z = rsqrtf(fmaxf(t.z, 1.f));
        r.w = rsqrtf(fmaxf(t.w, 1.f));
        ((float4*)g_deg)[bi] = r;
    }
}

// ---------------- K2: deterministic mask compaction ----------------
__global__ void compact_kernel(const int* __restrict__ mask) {
    __shared__ int woff[17];
    int b = blockIdx.x, t = threadIdx.x, lane = t & 31, w = t >> 5;
    int m = mask[b * NNODE + t];
    unsigned bal = __ballot_sync(0xffffffffu, m != 0);
    if (lane == 0) woff[w + 1] = __popc(bal);
    if (t == 0) woff[0] = 0;
    __syncthreads();
    if (t == 0) for (int k = 1; k <= 16; k++) woff[k] += woff[k - 1];
    __syncthreads();
    if (m) {
        int rank = woff[w] + __popc(bal & ((1u << lane) - 1u));
        g_idx[b * NNODE + rank] = t;
    }
    if (t == 0) g_cnt[b] = woff[16];
}

// ---------------- K3: build compacted normalized adjacency (Ac + Acc) ----------------
// one CTA (128 thr) per (b, compact row ri); reads only masked adj rows
__global__ __launch_bounds__(128)
void buildA_kernel(const float* __restrict__ adj) {
    int blk = blockIdx.x;
    int b = blk >> 9, ri = blk & (NNODE - 1);
    int cnt = g_cnt[b];
    if (ri >= cnt) return;
    int i = g_idx[b * NNODE + ri];
    int t = threadIdx.x;

    const float4* row = (const float4*)(adj + ((size_t)(b * NNODE + i)) * (NNODE * NEDGE));
    float4 di = ((const float4*)g_deg)[b * NNODE + i];

    __shared__ __nv_bfloat16 shi[NNODE], slo[NNODE];
    __shared__ __nv_bfloat16 schi[NNODE], sclo[NNODE];

#pragma unroll
    for (int q = 0; q < 4; q++) {
        int j = t + q * 128;
        float4 a = row[j];
        if (j == i) a = make_float4(1.f, 1.f, 1.f, 1.f);
        float4 dj = ((const float4*)g_deg)[b * NNODE + j];
        float v = a.x * di.x * dj.x + a.y * di.y * dj.y + a.z * di.z * dj.z + a.w * di.w * dj.w;
        __nv_bfloat16 hi = __float2bfloat16(v);
        shi[j] = hi;
        slo[j] = __float2bfloat16(v - __bfloat162float(hi));
    }
    __syncthreads();

    size_t rowOff = ((size_t)(b * NNODE + ri)) * NNODE;
    // Ac: full 512 cols, vector copy from smem (1KB per array)
    ((uint2*)(g_Achi + rowOff))[t] = ((const uint2*)shi)[t];
    ((uint2*)(g_Aclo + rowOff))[t] = ((const uint2*)slo)[t];

    // Acc: gather masked cols into compact order
    for (int rj = t; rj < cnt; rj += 128) {
        int j = g_idx[b * NNODE + rj];
        schi[rj] = shi[j];
        sclo[rj] = slo[j];
    }
    // zero tail up to 8B boundary
    int cntPad = (cnt + 3) & ~3;
    for (int rj = cnt + t; rj < cntPad; rj += 128) { schi[rj] = __float2bfloat16(0.f); sclo[rj] = __float2bfloat16(0.f); }
    __syncthreads();
    int nW = cntPad >> 2;   // uint2 count (4 bf16 each)
    for (int w2 = t; w2 < nW; w2 += 128) {
        ((uint2*)(g_Acchi + rowOff))[w2] = ((const uint2*)schi)[w2];
        ((uint2*)(g_Acclo + rowOff))[w2] = ((const uint2*)sclo)[w2];
    }
}

// ---------------- K4: lin: H[b][k][n] (hi/lo bf16) = X @ W ----------------
__global__ __launch_bounds__(256)
void lin_kernel(const float* __restrict__ X, const float* __restrict__ W, int K,
                __nv_bfloat16* __restrict__ Hhi, __nv_bfloat16* __restrict__ Hlo,
                const int* __restrict__ cnt) {
    int b  = blockIdx.x >> 2;
    int rt = blockIdx.x & 3;
    if (cnt && rt * 128 >= cnt[b]) return;   // compact mode: skip empty tiles
    const float* Xb = X + (size_t)(b * NNODE + rt * 128) * K;

    __shared__ float As[8][128];
    __shared__ float Bs[8][128];

    int tid = threadIdx.x;
    int tx = tid & 15, ty = tid >> 4;

    float acc[8][8];
#pragma unroll
    for (int u = 0; u < 8; u++)
#pragma unroll
        for (int v = 0; v < 8; v++) acc[u][v] = 0.f;

    int arow = tid >> 1, acol = (tid & 1) * 4;
    int brow = tid >> 5, bcol = (tid & 31) * 4;

    for (int k0 = 0; k0 < K; k0 += 8) {
        float4 a = *(const float4*)(Xb + (size_t)arow * K + k0 + acol);
        As[acol + 0][arow] = a.x;
        As[acol + 1][arow] = a.y;
        As[acol + 2][arow] = a.z;
        As[acol + 3][arow] = a.w;
        *(float4*)(&Bs[brow][bcol]) = *(const float4*)(W + (size_t)(k0 + brow) * CHID + bcol);
        __syncthreads();
#pragma unroll
        for (int kk = 0; kk < 8; kk++) {
            float ra[8], rb[8];
            *(float4*)(ra)     = *(const float4*)(&As[kk][ty * 8]);
            *(float4*)(ra + 4) = *(const float4*)(&As[kk][ty * 8 + 4]);
            *(float4*)(rb)     = *(const float4*)(&Bs[kk][tx * 8]);
            *(float4*)(rb + 4) = *(const float4*)(&Bs[kk][tx * 8 + 4]);
#pragma unroll
            for (int u = 0; u < 8; u++)
#pragma unroll
                for (int v = 0; v < 8; v++)
                    acc[u][v] = fmaf(ra[u], rb[v], acc[u][v]);
        }
        __syncthreads();
    }

#pragma unroll
    for (int u = 0; u < 8; u++) {
        int row = ty * 8 + u;
        size_t base = ((size_t)(b * NNODE + rt * 128 + row)) * CHID + tx * 8;
        __nv_bfloat16 hi8[8], lo8[8];
#pragma unroll
        for (int v = 0; v < 8; v++) {
            float val = acc[u][v];
            __nv_bfloat16 hi = __float2bfloat16(val);
            hi8[v] = hi;
            lo8[v] = __float2bfloat16(val - __bfloat162float(hi));
        }
        *(uint4*)(Hhi + base) = *(const uint4*)hi8;
        *(uint4*)(Hlo + base) = *(const uint4*)lo8;
    }
}

// ---------------- K5: mma.sync GCN GEMM on compacted rows ----------------
__device__ __forceinline__ void load_chunk(uint32_t st, int c, int tid,
                                           const char* Ah, const char* Al,
                                           const char* Bh, const char* Bl) {
#pragma unroll
    for (int i = 0; i < 2; i++) {
        int item = tid + i * 256;
        int row = item >> 2, seg = item & 3;
        uint32_t so = (uint32_t)(row * ASTR + seg * 16);
        size_t   go = (size_t)row * (NNODE * 2) + (size_t)c * (KC * 2) + seg * 16;
        cp16(st + OFF_AHI + so, Ah + go);
        cp16(st + OFF_ALO + so, Al + go);
    }
#pragma unroll
    for (int i = 0; i < 2; i++) {
        int item = tid + i * 256;
        int kr = item >> 4, seg = item & 15;
        uint32_t so = (uint32_t)(kr * HSTR + seg * 16);
        size_t   go = (size_t)(c * KC + kr) * (CHID * 2) + seg * 16;
        cp16(st + OFF_HHI + so, Bh + go);
        cp16(st + OFF_HLO + so, Bl + go);
    }
    CP_COMMIT();
}

template<bool POOL>
__global__ __launch_bounds__(256, 2)
void gcn_mma_kernel(const __nv_bfloat16* __restrict__ Ahi, const __nv_bfloat16* __restrict__ Alo,
                    const __nv_bfloat16* __restrict__ Hhi, const __nv_bfloat16* __restrict__ Hlo,
                    const float* __restrict__ bias, const int* __restrict__ cntArr,
                    int kfull, float* __restrict__ Hout, float* __restrict__ part) {
    int b = blockIdx.x >> 2, tile = blockIdx.x & 3;
    int cnt = cntArr[b];
    if (tile * 128 >= cnt) return;                       // nothing to compute (part stays 0)
    int nch = kfull ? (NNODE / KC) : ((((cnt + 127) >> 7) << 7) / KC);   // K chunks

    extern __shared__ char smem[];
    uint32_t sb = smem_u32(smem);
    int tid = threadIdx.x;
    int wid = tid >> 5, lane = tid & 31;
    int warpM = wid >> 2, warpN = wid & 3;

    const char* Ah = (const char*)Ahi + ((size_t)(b * NNODE + tile * 128)) * (NNODE * 2);
    const char* Al = (const char*)Alo + ((size_t)(b * NNODE + tile * 128)) * (NNODE * 2);
    const char* Bh = (const char*)Hhi + ((size_t)b * NNODE) * (CHID * 2);
    const char* Bl = (const char*)Hlo + ((size_t)b * NNODE) * (CHID * 2);

    uint32_t aRow = (uint32_t)((warpM * 64 + (lane & 15)) * ASTR + (lane >> 4) * 16);
    uint32_t bRow = (uint32_t)(((lane & 7) + ((lane >> 3) & 1) * 8) * HSTR
                               + (warpN * 32 + ((lane >> 4) & 1) * 8) * 2);

    load_chunk(sb, 0, tid, Ah, Al, Bh, Bl);
    load_chunk(sb + STAGEB, 1, tid, Ah, Al, Bh, Bl);

    float acc[4][4][4];
#pragma unroll
    for (int m = 0; m < 4; m++)
#pragma unroll
        for (int n = 0; n < 4; n++)
#pragma unroll
            for (int k = 0; k < 4; k++) acc[m][n][k] = 0.f;

    int stg = 0;
    for (int c = 0; c < nch; c++) {
        CP_WAIT1();
        __syncthreads();
        int pstg = stg + 2; if (pstg >= NSTG) pstg -= NSTG;
        if (c + 2 < nch)
            load_chunk(sb + (uint32_t)pstg * STAGEB, c + 2, tid, Ah, Al, Bh, Bl);
        else
            CP_COMMIT();
        uint32_t st = sb + (uint32_t)stg * STAGEB;
#pragma unroll
        for (int ks = 0; ks < KC / 16; ks++) {
            uint32_t ahi[4][4], alo[4][4];
#pragma unroll
            for (int mt = 0; mt < 4; mt++) {
                uint32_t ad = st + aRow + (uint32_t)(mt * 16 * ASTR + ks * 32);
                ldm_x4(ahi[mt][0], ahi[mt][1], ahi[mt][2], ahi[mt][3], ad + OFF_AHI);
                ldm_x4(alo[mt][0], alo[mt][1], alo[mt][2], alo[mt][3], ad + OFF_ALO);
            }
            uint32_t bhi[2][4], blo[2][4];
#pragma unroll
            for (int ng = 0; ng < 2; ng++) {
                uint32_t bd = st + bRow + (uint32_t)(ks * 16 * HSTR + ng * 32);
                ldm_x4t(bhi[ng][0], bhi[ng][1], bhi[ng][2], bhi[ng][3], bd + OFF_HHI);
                ldm_x4t(blo[ng][0], blo[ng][1], blo[ng][2], blo[ng][3], bd + OFF_HLO);
            }
#pragma unroll
            for (int mt = 0; mt < 4; mt++)
#pragma unroll
                for (int nt = 0; nt < 4; nt++) {
                    int ng = nt >> 1, hf = nt & 1;
                    mma16816(acc[mt][nt], ahi[mt], bhi[ng][hf * 2], bhi[ng][hf * 2 + 1]);
                    mma16816(acc[mt][nt], ahi[mt], blo[ng][hf * 2], blo[ng][hf * 2 + 1]);
                    mma16816(acc[mt][nt], alo[mt], bhi[ng][hf * 2], bhi[ng][hf * 2 + 1]);
                }
        }
        if (++stg >= NSTG) stg = 0;
    }

    // epilogue: bias + silu; rows >= cnt forced to exact 0 (pad rows)
    int lim = cnt - tile * 128;                     // valid rows in this tile
    int rowBase = b * NNODE + tile * 128 + warpM * 64;
    float* Ob = Hout + (size_t)rowBase * CHID;
    float csum[8];
#pragma unroll
    for (int k = 0; k < 8; k++) csum[k] = 0.f;

#pragma unroll
    for (int mt = 0; mt < 4; mt++) {
        int lr0 = warpM * 64 + mt * 16 + (lane >> 2);   // local row in tile
        bool ok0 = lr0 < lim;
        bool ok1 = (lr0 + 8) < lim;
#pragma unroll
        for (int nt = 0; nt < 4; nt++) {
            int col = warpN * 32 + nt * 8 + (lane & 3) * 2;
            float b0v = bias[col], b1v = bias[col + 1];
            float z0 = ok0 ? (acc[mt][nt][0] + b0v) : 0.f;
            float z1 = ok0 ? (acc[mt][nt][1] + b1v) : 0.f;
            float z2 = ok1 ? (acc[mt][nt][2] + b0v) : 0.f;
            float z3 = ok1 ? (acc[mt][nt][3] + b1v) : 0.f;
            float o0 = z0 / (1.f + __expf(-z0));
            float o1 = z1 / (1.f + __expf(-z1));
            float o2 = z2 / (1.f + __expf(-z2));
            float o3 = z3 / (1.f + __expf(-z3));
            if (POOL) {
                csum[nt * 2]     += o0 + o2;
                csum[nt * 2 + 1] += o1 + o3;
            } else {
                int r0 = mt * 16 + (lane >> 2);
                *(float2*)(Ob + (size_t)r0 * CHID + col)       = make_float2(o0, o1);
                *(float2*)(Ob + (size_t)(r0 + 8) * CHID + col) = make_float2(o2, o3);
            }
        }
    }

    if (POOL) {
        __shared__ float spool[2][CHID];
#pragma unroll
        for (int off = 4; off < 32; off <<= 1)
#pragma unroll
            for (int k = 0; k < 8; k++)
                csum[k] += __shfl_xor_sync(0xffffffffu, csum[k], off);
        if ((lane >> 2) == 0) {
#pragma unroll
            for (int nt = 0; nt < 4; nt++) {
                int col = warpN * 32 + nt * 8 + (lane & 3) * 2;
                spool[warpM][col]     = csum[nt * 2];
                spool[warpM][col + 1] = csum[nt * 2 + 1];
            }
        }
        __syncthreads();
        if (tid < CHID)
            part[(b * 4 + tile) * CHID + tid] = spool[0][tid] + spool[1][tid];
    }
}

// ---------------- K6: head from pooled partials ----------------
__global__ void head_kernel(const float* __restrict__ part,
                            const float* __restrict__ Wl1, const float* __restrict__ bl1,
                            const float* __restrict__ Wl2, const float* __restrict__ bl2,
                            float* __restrict__ out) {
    int b = blockIdx.x;
    int c = threadIdx.x;     // 128 threads
    __shared__ float g[CHID], g1[CHID];
    const float* pb = part + b * 4 * CHID;
    g[c] = (pb[c] + pb[CHID + c] + pb[2 * CHID + c] + pb[3 * CHID + c]) * (1.0f / NNODE);
    __syncthreads();
    float acc = bl1[c];
    for (int k = 0; k < CHID; k++) acc = fmaf(g[k], Wl1[k * CHID + c], acc);
    g1[c] = acc / (1.f + __expf(-acc));
    __syncthreads();
    if (c < COUT) {
        float acc2 = bl2[c];
        for (int k = 0; k < CHID; k++) acc2 = fmaf(g1[k], Wl2[k * COUT + c], acc2);
        out[b * COUT + c] = acc2;
    }
}

// ---------------- launch ----------------
extern "C" void kernel_launch(void* const* d_in, const int* in_sizes, int n_in,
                              void* d_out, int out_size) {
    const float* x    = (const float*)d_in[0];
    const float* adj  = (const float*)d_in[1];
    const int*   mask = (const int*)  d_in[2];
    const float* W0   = (const float*)d_in[3];
    const float* b0   = (const float*)d_in[4];
    const float* W1   = (const float*)d_in[5];
    const float* b1   = (const float*)d_in[6];
    const float* Wl1  = (const float*)d_in[7];
    const float* bl1  = (const float*)d_in[8];
    const float* Wl2  = (const float*)d_in[9];
    const float* bl2  = (const float*)d_in[10];
    float* out = (float*)d_out;

    __nv_bfloat16 *dAchi, *dAclo, *dAcchi, *dAcclo, *dHhi, *dHlo;
    float *dHout, *dPart;
    int *dCnt;
    cudaGetSymbolAddress((void**)&dAchi,  g_Achi);
    cudaGetSymbolAddress((void**)&dAclo,  g_Aclo);
    cudaGetSymbolAddress((void**)&dAcchi, g_Acchi);
    cudaGetSymbolAddress((void**)&dAcclo, g_Acclo);
    cudaGetSymbolAddress((void**)&dHhi,   g_Hhi);
    cudaGetSymbolAddress((void**)&dHlo,   g_Hlo);
    cudaGetSymbolAddress((void**)&dHout,  g_hout);
    cudaGetSymbolAddress((void**)&dPart,  g_part);
    cudaGetSymbolAddress((void**)&dCnt,   g_cnt);

    static int smem_set = 0;
    if (!smem_set) {
        cudaFuncSetAttribute(gcn_mma_kernel<false>,
                             cudaFuncAttributeMaxDynamicSharedMemorySize, SMEM_DYN);
        cudaFuncSetAttribute(gcn_mma_kernel<true>,
                             cudaFuncAttributeMaxDynamicSharedMemorySize, SMEM_DYN);
        smem_set = 1;
    }

    // 1) degrees (full pass: normalization needs all nodes)
    deg_kernel<<<BATCH * NNODE, 128>>>(adj);
    // 2) mask compaction (idx, cnt)
    compact_kernel<<<BATCH, NNODE>>>(mask);
    // 3) compacted normalized adjacency: Ac (rows compact) + Acc (rows+cols compact)
    buildA_kernel<<<BATCH * NNODE, 128>>>(adj);
    // 4) H = x @ W0 (dense, all nodes feed layer-1 K)
    lin_kernel<<<BATCH * 4, 256>>>(x, W0, CIN, dHhi, dHlo, nullptr);
    // 5) layer 1: compact rows, full K=512
    gcn_mma_kernel<false><<<BATCH * 4, 256, SMEM_DYN>>>(dAchi, dAclo, dHhi, dHlo, b0,
                                                        dCnt, 1, dHout, dPart);
    // 6) Hc = h1c @ W1 (compact rows)
    lin_kernel<<<BATCH * 4, 256>>>(dHout, W1, CHID, dHhi, dHlo, dCnt);
    // 7) layer 2: compact rows AND compact K, fused mean-pool
    gcn_mma_kernel<true><<<BATCH * 4, 256, SMEM_DYN>>>(dAcchi, dAcclo, dHhi, dHlo, b1,
                                                       dCnt, 0, dHout, dPart);
    // 8) MLP head
    head_kernel<<<BATCH, CHID>>>(dPart, Wl1, bl1, Wl2, bl2, out);
}